// round 12
// baseline (speedup 1.0000x reference)
#include <cuda_runtime.h>
#include <math.h>

typedef unsigned long long ULL;
typedef unsigned int U32;

#define NB 2
#define NS 2048
#define NE 1024
#define NH 16
#define NHD 64
#define NM 4096                  // NB*NS
#define ATT_SCALE (1.0f/32.0f)   // 1/sqrt(1024), exact power of two

// ---------------- scratch (device globals; no allocation allowed) ----------
__device__ float g_q[NB*NH*NS*NHD];    // head-major: [b*16+h][s][hd]
__device__ float g_k[NB*NH*NS*NHD];
__device__ float g_v[NB*NH*NS*NHD];
__device__ float g_ctx[NB*NH*NS*NHD];  // written tf32-rounded by flash
__device__ float g_cos[NS*32];
__device__ float g_sin[NS*32];
// pre-converted tf32-bit operands
__device__ U32 g_qc[NM*NE];
__device__ U32 g_kc[NM*NE];
__device__ U32 g_vc[NM*NE];
__device__ U32 g_wqc[NE*NE];
__device__ U32 g_wkc[NE*NE];
__device__ U32 g_wvc[NE*NE];
__device__ U32 g_woc[NE*NE];
// K/V pre-packed into flash B-layout smem images: [bh][kb][4096 U32]
__device__ U32 g_kt[NB*NH*32*4096];
__device__ U32 g_vt[NB*NH*32*4096];

// ---------------- helpers ---------------------------------------------------
__device__ __forceinline__ U32 f2tf(float x){
    U32 u; asm("cvt.rn.tf32.f32 %0, %1;" : "=r"(u) : "f"(x)); return u;
}
__device__ __forceinline__ void mma8(float* c, const U32* a, const U32* b){
    asm volatile("mma.sync.aligned.m16n8k8.row.col.f32.tf32.tf32.f32 "
        "{%0,%1,%2,%3}, {%4,%5,%6,%7}, {%8,%9}, {%0,%1,%2,%3};"
        : "+f"(c[0]), "+f"(c[1]), "+f"(c[2]), "+f"(c[3])
        : "r"(a[0]), "r"(a[1]), "r"(a[2]), "r"(a[3]), "r"(b[0]), "r"(b[1]));
}
__device__ __forceinline__ U32 smem_u32(const void* p){
    U32 a;
    asm("{ .reg .u64 t; cvta.to.shared.u64 t, %1; cvt.u32.u64 %0, t; }"
        : "=r"(a) : "l"(p));
    return a;
}
__device__ __forceinline__ void ldsm4(U32* r, U32 a){
    asm volatile("ldmatrix.sync.aligned.m8n8.x4.shared.b16 {%0,%1,%2,%3}, [%4];"
        : "=r"(r[0]), "=r"(r[1]), "=r"(r[2]), "=r"(r[3]) : "r"(a));
}
__device__ __forceinline__ void ldsm2(U32* r, U32 a){
    asm volatile("ldmatrix.sync.aligned.m8n8.x2.shared.b16 {%0,%1}, [%2];"
        : "=r"(r[0]), "=r"(r[1]) : "r"(a));
}
__device__ __forceinline__ void cpa16(U32 dst, const void* src){
    asm volatile("cp.async.cg.shared.global [%0], [%1], 16;"
                 :: "r"(dst), "l"(src) : "memory");
}

// ---------------- prep: fp32 -> tf32 bits (RN) ------------------------------
#define Q4 (NM*NE/4)
#define W4 (NE*NE/4)
__global__ void prep_kernel(const float4* __restrict__ q, const float4* __restrict__ k,
                            const float4* __restrict__ v, const float4* __restrict__ wq,
                            const float4* __restrict__ wk, const float4* __restrict__ wv,
                            const float4* __restrict__ wo)
{
    int i = blockIdx.x * blockDim.x + threadIdx.x;
    const float4* s; uint4* d;
    if      (i <   Q4) { s = q + i;        d = (uint4*)g_qc + i; }
    else if (i < 2*Q4) { s = k + (i-Q4);   d = (uint4*)g_kc + (i-Q4); }
    else if (i < 3*Q4) { s = v + (i-2*Q4); d = (uint4*)g_vc + (i-2*Q4); }
    else {
        int j = i - 3*Q4, w = j / W4, o = j - w*W4;
        const float4* ws[4] = {wq, wk, wv, wo};
        uint4* wd[4] = {(uint4*)g_wqc, (uint4*)g_wkc, (uint4*)g_wvc, (uint4*)g_woc};
        s = ws[w] + o; d = wd[w] + o;
    }
    float4 f = *s;
    *d = make_uint4(f2tf(f.x), f2tf(f.y), f2tf(f.z), f2tf(f.w));
}

// ---------------- kvprep: pack K/V tiles into flash B-layout ----------------
__global__ void __launch_bounds__(256)
kvprep_kernel()
{
    __shared__ float sm[64][68];
    const int kb = blockIdx.x, bh = blockIdx.y, mode = blockIdx.z;
    const int t  = threadIdx.x;
    const float* src = (mode ? g_v : g_k) + (size_t)bh*NS*64 + (size_t)kb*64*64;
    U32* dst = (mode ? g_vt : g_kt) + ((size_t)bh*32 + kb)*4096;

    #pragma unroll
    for (int it = 0; it < 4; ++it) {
        int i4 = it*256 + t;
        int row = i4 >> 4, c4 = i4 & 15;
        float4 f = *(const float4*)(src + row*64 + c4*4);
        sm[row][c4*4+0]=f.x; sm[row][c4*4+1]=f.y;
        sm[row][c4*4+2]=f.z; sm[row][c4*4+3]=f.w;
    }
    __syncthreads();

    #pragma unroll
    for (int it = 0; it < 4; ++it) {
        int ch = it*256 + t;
        int off = ch * 16;
        int o  = off >> 11;
        int r1 = off & 2047;
        int nf = r1 >> 8;
        int g  = (r1 >> 5) & 7;
        int w0 = (off & 31) >> 3;
        int swb = ((g>>2)&1) | ((nf&1)<<1);
        uint4 u;
        if (mode == 0) {
            int c = nf*8 + g;
            int tg0 = w0 ^ swb ^ (o&3), tg1 = (w0+1) ^ swb ^ (o&3);
            u.x = f2tf(sm[c][o*8 + tg0]);
            u.y = f2tf(sm[c][o*8 + tg0 + 4]);
            u.z = f2tf(sm[c][o*8 + tg1]);
            u.w = f2tf(sm[c][o*8 + tg1 + 4]);
        } else {
            int n = nf*8 + g;
            int tg0 = w0 ^ swb ^ (o&3), tg1 = (w0+1) ^ swb ^ (o&3);
            u.x = f2tf(sm[o*8 + tg0][n]);
            u.y = f2tf(sm[o*8 + tg0 + 4][n]);
            u.z = f2tf(sm[o*8 + tg1][n]);
            u.w = f2tf(sm[o*8 + tg1 + 4][n]);
        }
        *(uint4*)(dst + ch*4) = u;
    }
}

// ============================================================================
// Projection GEMM v6: BK=32 (two BK-16 sub-images per stage), cp.async
// 3-stage, ldmatrix. 256 thr = 8 warps (2x4), warp tile 64x32.
// Stage = [A0 8K][B0 8K][A1 8K][B1 8K] = 32KB; 3 stages = 96KB dynamic.
// ============================================================================
#define PST 32768                // bytes per stage
#define GSM_BYTES (3*PST)

__global__ void __launch_bounds__(256, 2)
gemm_mma(const U32* __restrict__ A, const U32* __restrict__ Wt,
         float* __restrict__ C, int a_heads, int c_heads, int do_rope)
{
    extern __shared__ __align__(128) char smem[];
    const U32 sb0 = smem_u32(smem);
    const int t    = threadIdx.x;
    const int lane = t & 31;
    const int wid  = t >> 5;
    const int grp  = lane >> 2;
    const int tig  = lane & 3;
    const int wm   = (wid & 1) * 64;
    const int wn   = (wid >> 1) * 32;
    const int bm   = blockIdx.y * 128;
    const int bn   = blockIdx.x * 128;

    const int prA = t >> 1, prH = t & 1;
    const U32 dsw0 = prA*64 + (((2*prH    ) ^ ((prA>>1)&3)) << 4);
    const U32 dsw1 = prA*64 + (((2*prH + 1) ^ ((prA>>1)&3)) << 4);

    const int rlA = (lane & 7) | (((lane >> 3) & 1) << 3);
    const int cbA = (lane >> 4) & 1;
    const U32 offA = sb0 + (wm + rlA)*64 + ((cbA ^ ((rlA>>1)&3)) << 4);
    const int rlB = lane & 7;
    const int cbB = (lane >> 3) & 1;
    const U32 offB = sb0 + 8192 + (wn + rlB)*64 + ((cbB ^ ((rlB>>1)&3)) << 4);

    float acc[4][4][4];
    #pragma unroll
    for (int i=0;i<4;++i)
        #pragma unroll
        for (int j=0;j<4;++j)
            #pragma unroll
            for (int r=0;r<4;++r) acc[i][j][r] = 0.0f;

    auto CPA = [&](int kt, int st){
        #pragma unroll
        for (int sub = 0; sub < 2; ++sub) {
            const U32 sA = sb0 + st*PST + sub*16384;
            const U32 sB = sA + 8192;
            const int e0 = kt*32 + sub*16 + prH*8;
            const U32* pa;
            if (!a_heads) pa = A + (size_t)(bm + prA)*NE + e0;
            else {
                int m = bm + prA, b = m >> 11, s = m & 2047;
                pa = A + ((size_t)((b*16 + (e0 >> 6))*NS + s))*64 + (e0 & 63);
            }
            const U32* pb = Wt + (size_t)(bn + prA)*NE + e0;
            cpa16(sA + dsw0, pa);     cpa16(sA + dsw1, pa + 4);
            cpa16(sB + dsw0, pb);     cpa16(sB + dsw1, pb + 4);
        }
        asm volatile("cp.async.commit_group;" ::: "memory");
    };

    auto MMA = [&](int st){
        #pragma unroll
        for (int sub = 0; sub < 2; ++sub) {
            const U32 bA = offA + st*PST + sub*16384;
            const U32 bB = offB + st*PST + sub*16384;
            #pragma unroll
            for (int ks = 0; ks < 2; ++ks) {
                U32 af[4][4];
                #pragma unroll
                for (int mf = 0; mf < 4; ++mf)
                    ldsm4(af[mf], (bA + mf*1024) ^ (ks << 5));
                U32 bf[4][2];
                #pragma unroll
                for (int nf = 0; nf < 4; ++nf)
                    ldsm2(bf[nf], (bB + nf*512) ^ (ks << 5));
                #pragma unroll
                for (int mf = 0; mf < 4; ++mf)
                    #pragma unroll
                    for (int nf = 0; nf < 4; ++nf)
                        mma8(acc[mf][nf], af[mf], bf[nf]);
            }
        }
    };

    CPA(0, 0); CPA(1, 1);
    for (int kt = 0; kt < 32; ++kt) {
        if (kt < 31) asm volatile("cp.async.wait_group 1;" ::: "memory");
        else         asm volatile("cp.async.wait_group 0;" ::: "memory");
        __syncthreads();
        if (kt < 30) CPA(kt + 2, (kt + 2) % 3);
        MMA(kt % 3);
    }

    #pragma unroll
    for (int mf = 0; mf < 4; ++mf) {
        #pragma unroll
        for (int half = 0; half < 2; ++half) {
            int m = bm + wm + mf*16 + grp + half*8;
            #pragma unroll
            for (int nf = 0; nf < 4; ++nf) {
                int n = bn + wn + nf*8 + 2*tig;
                float fx = acc[mf][nf][half*2 + 0];
                float fy = acc[mf][nf][half*2 + 1];
                if (do_rope) {
                    int s = m & 2047;
                    int p = (n & 63) >> 1;
                    float co = g_cos[s*32 + p], sn = g_sin[s*32 + p];
                    float rx = fx*co - fy*sn;
                    float ry = fx*sn + fy*co;
                    fx = rx; fy = ry;
                }
                float2 f = make_float2(fx, fy);
                if (!c_heads) {
                    *(float2*)(C + (size_t)m*NE + n) = f;
                } else {
                    int b = m >> 11, s2 = m & 2047;
                    *(float2*)(C + ((size_t)((b*16 + (n>>6))*NS + s2))*64 + (n & 63)) = f;
                }
            }
        }
    }
}

// ---------------- RoPE table -----------------------------------------------
__global__ void rope_table_kernel()
{
    int idx = blockIdx.x * blockDim.x + threadIdx.x;
    if (idx >= NS*32) return;
    int s = idx >> 5, p = idx & 31;
    double invf = 1.0 / pow(10000.0, (double)(2*p) / 64.0);
    double a = (double)s * invf;
    g_cos[idx] = (float)cos(a);
    g_sin[idx] = (float)sin(a);
}

// ============================================================================
// Flash attention v4: q-tile 128 (256 thr = 8 warps x 16 rows), K/V streamed
// via cp.async from pre-packed g_kt/g_vt, 2-stage double buffer.
// Dynamic smem: Ks[2][16KB] + Vs[2][16KB] + Ps[32KB] = 96KB.
// A-layout (128 rows): addr = ks*4096 + mf*512 + grp*64 + swz-chunk + ...
// ============================================================================
#define FLS_BYTES (32768 + 32768 + 32768)

__global__ void __launch_bounds__(256)
flash_mma_kernel()
{
    extern __shared__ __align__(128) char fsm[];
    char* Ks = fsm;                      // 2 stages x 16KB
    char* Vs = fsm + 32768;              // 2 stages x 16KB
    char* Ps = fsm + 65536;              // A-layout P^T (128x64); Q staging

    const int t    = threadIdx.x;
    const int lane = t & 31;
    const int wid  = t >> 5;             // 0..7
    const int grp  = lane >> 2;
    const int tig  = lane & 3;
    const int wr   = wid * 16;
    const int mfW  = wid;
    const int tigA = tig ^ ((grp >> 1) & 3);
    const int bh   = blockIdx.y;
    const int qt   = (int)gridDim.x - 1 - (int)blockIdx.x;  // heavy first
    const int q0   = qt * 128;
    const int kbmax = 2*qt + 1;

    const float* qp = g_q + (size_t)bh * NS * 64;
    const U32* ktp = g_kt + (size_t)bh * 32 * 4096;
    const U32* vtp = g_vt + (size_t)bh * 32 * 4096;
    const U32 sbK = smem_u32(Ks);
    const U32 sbV = smem_u32(Vs);

    auto CPAKV = [&](int kb, int st){
        const U32 dK = sbK + st*16384;
        const U32 dV = sbV + st*16384;
        const U32* sK = ktp + (size_t)kb*4096;
        const U32* sV = vtp + (size_t)kb*4096;
        #pragma unroll
        for (int i = 0; i < 4; ++i) {
            int c = i*256 + t;
            cpa16(dK + c*16, sK + c*4);
            cpa16(dV + c*16, sV + c*4);
        }
        asm volatile("cp.async.commit_group;" ::: "memory");
    };

    // ---- stage Q (scaled) into Ps using A-layout (128 rows) ----
    {
        const int r = t >> 1, ksP = t & 1;
        const int mf = r >> 4, g = r & 7, hi = (r >> 3) & 1;
        const int swz = (g >> 1) & 3;
        const float* pq = qp + (size_t)(q0 + r)*64 + ksP*32;
        char* base = Ps + mf*512 + g*64 + hi*4;
        #pragma unroll
        for (int j8 = 0; j8 < 4; ++j8) {
            float4 f0 = *(const float4*)(pq + j8*8);
            float4 f1 = *(const float4*)(pq + j8*8 + 4);
            int ks = ksP*4 + j8;
            float vals[8] = {f0.x,f0.y,f0.z,f0.w,f1.x,f1.y,f1.z,f1.w};
            #pragma unroll
            for (int j = 0; j < 8; ++j) {
                int tg = j & 3, khi = j >> 2;
                *(U32*)(base + ks*4096 + ((tg^swz)<<4) + khi*8) =
                    f2tf(vals[j] * ATT_SCALE);
            }
        }
    }
    CPAKV(0, 0);
    __syncthreads();

    // ---- Q fragments -> registers ----
    U32 qf[8][4];
    #pragma unroll
    for (int ks = 0; ks < 8; ++ks)
        *(uint4*)qf[ks] =
            *(const uint4*)(Ps + ks*4096 + mfW*512 + grp*64 + (tigA<<4));

    float m_[2], l_[2];
    m_[0] = m_[1] = -1e30f;
    l_[0] = l_[1] = 0.0f;
    float octx[8][4];
    #pragma unroll
    for (int nf=0;nf<8;++nf)
        #pragma unroll
        for (int r=0;r<4;++r) octx[nf][r] = 0.0f;

    for (int kb = 0; kb <= kbmax; ++kb) {
        const int st = kb & 1;
        if (kb < kbmax) CPAKV(kb + 1, (kb + 1) & 1);
        if (kb < kbmax) asm volatile("cp.async.wait_group 1;" ::: "memory");
        else            asm volatile("cp.async.wait_group 0;" ::: "memory");
        __syncthreads();

        const int k0 = kb * 64;
        char* Kc = Ks + st*16384;
        char* Vc = Vs + st*16384;

        // ---- S = Q @ K^T ----
        float sacc[8][4];
        #pragma unroll
        for (int nf=0;nf<8;++nf)
            #pragma unroll
            for (int r=0;r<4;++r) sacc[nf][r] = 0.0f;
        #pragma unroll
        for (int ks = 0; ks < 8; ++ks) {
            #pragma unroll
            for (int nf = 0; nf < 8; ++nf) {
                int tb = tig ^ (((grp>>2)&1) | ((nf&1)<<1)) ^ (ks&3);
                uint2 bf = *(const uint2*)(Kc + ks*2048 + nf*256
                                              + grp*32 + (tb<<3));
                mma8(sacc[nf], qf[ks], (const U32*)&bf);
            }
        }

        // ---- online softmax; write P^T in A-layout ----
        const bool mz = (kb >= 2*qt);    // mask zone: last two kv tiles
        #pragma unroll
        for (int l = 0; l < 2; ++l) {
            const int rloc = wr + grp + 8*l;
            const int gi   = q0 + rloc;
            float rm = -1e30f;
            #pragma unroll
            for (int nf = 0; nf < 8; ++nf) {
                #pragma unroll
                for (int c = 0; c < 2; ++c) {
                    float s = sacc[nf][2*l + c];
                    if (mz) {
                        int gj = k0 + nf*8 + 2*tig + c;
                        if (gj >= gi && !(gi == 0 && gj == 0)) s = -1e30f;
                    }
                    sacc[nf][2*l + c] = s;
                    rm = fmaxf(rm, s);
                }
            }
            rm = fmaxf(rm, __shfl_xor_sync(0xffffffffu, rm, 1));
            rm = fmaxf(rm, __shfl_xor_sync(0xffffffffu, rm, 2));
            float mnew = fmaxf(m_[l], rm);
            float fac  = __expf(m_[l] - mnew);
            float ps = 0.0f;
            char* pbase = Ps + mfW*512 + grp*64 + l*4;
            const int swzP = (grp >> 1) & 3;
            #pragma unroll
            for (int nf = 0; nf < 8; ++nf) {
                #pragma unroll
                for (int c = 0; c < 2; ++c) {
                    float p = __expf(sacc[nf][2*l + c] - mnew);
                    int j = 2*tig + c;
                    int tg = j & 3, khi = j >> 2;
                    *(U32*)(pbase + nf*4096 + ((tg^swzP)<<4) + khi*8) = f2tf(p);
                    ps += p;
                }
            }
            ps += __shfl_xor_sync(0xffffffffu, ps, 1);
            ps += __shfl_xor_sync(0xffffffffu, ps, 2);
            l_[l] = l_[l]*fac + ps;
            m_[l] = mnew;
            #pragma unroll
            for (int nf = 0; nf < 8; ++nf) {
                octx[nf][2*l + 0] *= fac;
                octx[nf][2*l + 1] *= fac;
            }
        }
        __syncwarp();                    // P^T region is warp-private

        // ---- ctx += P @ V ----
        #pragma unroll
        for (int ks = 0; ks < 8; ++ks) {
            uint4 af = *(const uint4*)(Ps + ks*4096 + mfW*512
                                          + grp*64 + (tigA<<4));
            #pragma unroll
            for (int nf = 0; nf < 8; ++nf) {
                int tb = tig ^ (((grp>>2)&1) | ((nf&1)<<1)) ^ (ks&3);
                uint2 bf = *(const uint2*)(Vc + ks*2048 + nf*256
                                              + grp*32 + (tb<<3));
                mma8(octx[nf], (const U32*)&af, (const U32*)&bf);
            }
        }
        __syncthreads();                 // all warps done with buffer st
    }

    // ---- normalize + write ctx tf32-rounded (head-major) ----
    U32* op = (U32*)(g_ctx + (size_t)bh * NS * 64);
    #pragma unroll
    for (int l = 0; l < 2; ++l) {
        const int r  = q0 + wr + grp + 8*l;
        const float inv = 1.0f / l_[l];
        #pragma unroll
        for (int nf = 0; nf < 8; ++nf) {
            uint2 u;
            u.x = f2tf(octx[nf][2*l + 0] * inv);
            u.y = f2tf(octx[nf][2*l + 1] * inv);
            *(uint2*)(op + (size_t)r*64 + nf*8 + 2*tig) = u;
        }
    }
}

// ---------------------------------------------------------------------------
extern "C" void kernel_launch(void* const* d_in, const int* in_sizes, int n_in,
                              void* d_out, int out_size)
{
    const float* q  = (const float*)d_in[0];
    const float* k  = (const float*)d_in[1];
    const float* v  = (const float*)d_in[2];
    const float* Wq = (const float*)d_in[3];
    const float* Wk = (const float*)d_in[4];
    const float* Wv = (const float*)d_in[5];
    const float* Wo = (const float*)d_in[6];
    float* out = (float*)d_out;

    float *pq, *pk, *pv, *pctx;
    cudaGetSymbolAddress((void**)&pq,   g_q);
    cudaGetSymbolAddress((void**)&pk,   g_k);
    cudaGetSymbolAddress((void**)&pv,   g_v);
    cudaGetSymbolAddress((void**)&pctx, g_ctx);
    U32 *pqc, *pkc, *pvc, *pwq, *pwk, *pwv, *pwo;
    cudaGetSymbolAddress((void**)&pqc, g_qc);
    cudaGetSymbolAddress((void**)&pkc, g_kc);
    cudaGetSymbolAddress((void**)&pvc, g_vc);
    cudaGetSymbolAddress((void**)&pwq, g_wqc);
    cudaGetSymbolAddress((void**)&pwk, g_wkc);
    cudaGetSymbolAddress((void**)&pwv, g_wvc);
    cudaGetSymbolAddress((void**)&pwo, g_woc);

    cudaFuncSetAttribute(flash_mma_kernel,
                         cudaFuncAttributeMaxDynamicSharedMemorySize,
                         FLS_BYTES);
    cudaFuncSetAttribute(gemm_mma,
                         cudaFuncAttributeMaxDynamicSharedMemorySize,
                         GSM_BYTES);

    rope_table_kernel<<<256, 256>>>();
    prep_kernel<<<(3*Q4 + 4*W4)/256, 256>>>((const float4*)q, (const float4*)k,
        (const float4*)v, (const float4*)Wq, (const float4*)Wk,
        (const float4*)Wv, (const float4*)Wo);

    dim3 gg(NE/128, NM/128);               // (8, 32)
    gemm_mma<<<gg, 256, GSM_BYTES>>>(pqc, pwq, pq, 0, 1, 1);   // Q proj + RoPE
    gemm_mma<<<gg, 256, GSM_BYTES>>>(pkc, pwk, pk, 0, 1, 1);   // K proj + RoPE
    gemm_mma<<<gg, 256, GSM_BYTES>>>(pvc, pwv, pv, 0, 1, 0);   // V proj

    dim3 kvg(32, NB*NH, 2);
    kvprep_kernel<<<kvg, 256>>>();         // pack K/V into B-layout tiles

    dim3 fg(NS/128, NB*NH);                // (16, 32)
    flash_mma_kernel<<<fg, 256, FLS_BYTES>>>();

    gemm_mma<<<gg, 256, GSM_BYTES>>>((const U32*)pctx, pwo, out, 1, 0, 0);
}

// round 13
// speedup vs baseline: 1.0941x; 1.0941x over previous
#include <cuda_runtime.h>
#include <math.h>

typedef unsigned long long ULL;
typedef unsigned int U32;

#define NB 2
#define NS 2048
#define NE 1024
#define NH 16
#define NHD 64
#define NM 4096                  // NB*NS
#define ATT_SCALE (1.0f/32.0f)   // 1/sqrt(1024), exact power of two

// ---------------- scratch (device globals; no allocation allowed) ----------
__device__ float g_q[NB*NH*NS*NHD];    // head-major: [b*16+h][s][hd]
__device__ float g_ctx[NB*NH*NS*NHD];  // written tf32-rounded by flash
__device__ float g_cos[NS*32];
__device__ float g_sin[NS*32];
// pre-converted tf32-bit operands
__device__ U32 g_qc[NM*NE];
__device__ U32 g_kc[NM*NE];
__device__ U32 g_vc[NM*NE];
__device__ U32 g_wqc[NE*NE];
__device__ U32 g_wkc[NE*NE];
__device__ U32 g_wvc[NE*NE];
__device__ U32 g_woc[NE*NE];
// K/V packed into flash B-layout smem images: [bh][kb][4096 U32]
__device__ U32 g_kt[NB*NH*32*4096];
__device__ U32 g_vt[NB*NH*32*4096];

// ---------------- helpers ---------------------------------------------------
__device__ __forceinline__ U32 f2tf(float x){
    U32 u; asm("cvt.rn.tf32.f32 %0, %1;" : "=r"(u) : "f"(x)); return u;
}
__device__ __forceinline__ void mma8(float* c, const U32* a, const U32* b){
    asm volatile("mma.sync.aligned.m16n8k8.row.col.f32.tf32.tf32.f32 "
        "{%0,%1,%2,%3}, {%4,%5,%6,%7}, {%8,%9}, {%0,%1,%2,%3};"
        : "+f"(c[0]), "+f"(c[1]), "+f"(c[2]), "+f"(c[3])
        : "r"(a[0]), "r"(a[1]), "r"(a[2]), "r"(a[3]), "r"(b[0]), "r"(b[1]));
}
__device__ __forceinline__ U32 smem_u32(const void* p){
    U32 a;
    asm("{ .reg .u64 t; cvta.to.shared.u64 t, %1; cvt.u32.u64 %0, t; }"
        : "=r"(a) : "l"(p));
    return a;
}
__device__ __forceinline__ void ldsm4(U32* r, U32 a){
    asm volatile("ldmatrix.sync.aligned.m8n8.x4.shared.b16 {%0,%1,%2,%3}, [%4];"
        : "=r"(r[0]), "=r"(r[1]), "=r"(r[2]), "=r"(r[3]) : "r"(a));
}
__device__ __forceinline__ void ldsm2(U32* r, U32 a){
    asm volatile("ldmatrix.sync.aligned.m8n8.x2.shared.b16 {%0,%1}, [%2];"
        : "=r"(r[0]), "=r"(r[1]) : "r"(a));
}
__device__ __forceinline__ void cpa16(U32 dst, const void* src){
    asm volatile("cp.async.cg.shared.global [%0], [%1], 16;"
                 :: "r"(dst), "l"(src) : "memory");
}

// ---------------- prep: fp32 -> tf32 bits (RN) ------------------------------
#define Q4 (NM*NE/4)
#define W4 (NE*NE/4)
__global__ void prep_kernel(const float4* __restrict__ q, const float4* __restrict__ k,
                            const float4* __restrict__ v, const float4* __restrict__ wq,
                            const float4* __restrict__ wk, const float4* __restrict__ wv,
                            const float4* __restrict__ wo)
{
    int i = blockIdx.x * blockDim.x + threadIdx.x;
    const float4* s; uint4* d;
    if      (i <   Q4) { s = q + i;        d = (uint4*)g_qc + i; }
    else if (i < 2*Q4) { s = k + (i-Q4);   d = (uint4*)g_kc + (i-Q4); }
    else if (i < 3*Q4) { s = v + (i-2*Q4); d = (uint4*)g_vc + (i-2*Q4); }
    else {
        int j = i - 3*Q4, w = j / W4, o = j - w*W4;
        const float4* ws[4] = {wq, wk, wv, wo};
        uint4* wd[4] = {(uint4*)g_wqc, (uint4*)g_wkc, (uint4*)g_wvc, (uint4*)g_woc};
        s = ws[w] + o; d = wd[w] + o;
    }
    float4 f = *s;
    *d = make_uint4(f2tf(f.x), f2tf(f.y), f2tf(f.z), f2tf(f.w));
}

// ============================================================================
// Projection GEMM (R10/R11, proven): cp.async 3-stage + ldmatrix, BK=16.
// 256 thr = 8 warps (2x4), warp tile 64x32. Static smem 48KB.
// Epilogue modes: 0=plain C [m][n]; 1=head-major fp32 (Q);
//                 2=K packed into g_kt; 3=V packed into g_vt.
// ============================================================================
#define PST 16384

__global__ void __launch_bounds__(256, 2)
gemm_mma(const U32* __restrict__ A, const U32* __restrict__ Wt,
         float* __restrict__ C, int a_heads, int mode, int do_rope)
{
    __shared__ __align__(128) char smem[3*PST];
    const U32 sb0 = smem_u32(smem);
    const int t    = threadIdx.x;
    const int lane = t & 31;
    const int wid  = t >> 5;
    const int grp  = lane >> 2;
    const int tig  = lane & 3;
    const int wm   = (wid & 1) * 64;
    const int wn   = (wid >> 1) * 32;
    const int bm   = blockIdx.y * 128;
    const int bn   = blockIdx.x * 128;

    const int prA = t >> 1, prH = t & 1;
    const U32 dsw0 = prA*64 + (((2*prH    ) ^ ((prA>>1)&3)) << 4);
    const U32 dsw1 = prA*64 + (((2*prH + 1) ^ ((prA>>1)&3)) << 4);

    const int rlA = (lane & 7) | (((lane >> 3) & 1) << 3);
    const int cbA = (lane >> 4) & 1;
    const U32 offA = sb0 + (wm + rlA)*64 + ((cbA ^ ((rlA>>1)&3)) << 4);
    const int rlB = lane & 7;
    const int cbB = (lane >> 3) & 1;
    const U32 offB = sb0 + 8192 + (wn + rlB)*64 + ((cbB ^ ((rlB>>1)&3)) << 4);

    float acc[4][4][4];
    #pragma unroll
    for (int i=0;i<4;++i)
        #pragma unroll
        for (int j=0;j<4;++j)
            #pragma unroll
            for (int r=0;r<4;++r) acc[i][j][r] = 0.0f;

    auto CPA = [&](int kt, int st){
        const U32 sA = sb0 + st*PST;
        const U32 sB = sA + 8192;
        const int e0 = kt*16 + prH*8;
        const U32* pa;
        if (!a_heads) pa = A + (size_t)(bm + prA)*NE + e0;
        else {
            int m = bm + prA, b = m >> 11, s = m & 2047;
            pa = A + ((size_t)((b*16 + (e0 >> 6))*NS + s))*64 + (e0 & 63);
        }
        const U32* pb = Wt + (size_t)(bn + prA)*NE + e0;
        cpa16(sA + dsw0, pa);     cpa16(sA + dsw1, pa + 4);
        cpa16(sB + dsw0, pb);     cpa16(sB + dsw1, pb + 4);
        asm volatile("cp.async.commit_group;" ::: "memory");
    };

    auto MMA = [&](int st){
        const U32 bA = offA + st*PST;
        const U32 bB = offB + st*PST;
        #pragma unroll
        for (int ks = 0; ks < 2; ++ks) {
            U32 af[4][4];
            #pragma unroll
            for (int mf = 0; mf < 4; ++mf)
                ldsm4(af[mf], (bA + mf*1024) ^ (ks << 5));
            U32 bf[4][2];
            #pragma unroll
            for (int nf = 0; nf < 4; ++nf)
                ldsm2(bf[nf], (bB + nf*512) ^ (ks << 5));
            #pragma unroll
            for (int mf = 0; mf < 4; ++mf)
                #pragma unroll
                for (int nf = 0; nf < 4; ++nf)
                    mma8(acc[mf][nf], af[mf], bf[nf]);
        }
    };

    CPA(0, 0); CPA(1, 1);
    for (int kt = 0; kt < 64; ++kt) {
        if (kt < 63) asm volatile("cp.async.wait_group 1;" ::: "memory");
        else         asm volatile("cp.async.wait_group 0;" ::: "memory");
        __syncthreads();
        if (kt < 62) CPA(kt + 2, (kt + 2) % 3);
        MMA(kt % 3);
    }

    // epilogue (+ optional fused RoPE: (fx,fy) = one (even,odd) hd pair)
    #pragma unroll
    for (int mf = 0; mf < 4; ++mf) {
        #pragma unroll
        for (int half = 0; half < 2; ++half) {
            int m = bm + wm + mf*16 + grp + half*8;
            #pragma unroll
            for (int nf = 0; nf < 4; ++nf) {
                int n = bn + wn + nf*8 + 2*tig;
                float fx = acc[mf][nf][half*2 + 0];
                float fy = acc[mf][nf][half*2 + 1];
                if (do_rope) {
                    int s = m & 2047;
                    int p = (n & 63) >> 1;
                    float co = g_cos[s*32 + p], sn = g_sin[s*32 + p];
                    float rx = fx*co - fy*sn;
                    float ry = fx*sn + fy*co;
                    fx = rx; fy = ry;
                }
                if (mode == 0) {
                    *(float2*)(C + (size_t)m*NE + n) = make_float2(fx, fy);
                } else if (mode == 1) {
                    int b = m >> 11, s2 = m & 2047;
                    *(float2*)(C + ((size_t)((b*16 + (n>>6))*NS + s2))*64 + (n & 63))
                        = make_float2(fx, fy);
                } else if (mode == 2) {
                    // K packed: element K[s][hd] -> g_kt B-layout
                    int b = m >> 11, s2 = m & 2047;
                    int h = n >> 6, hd = n & 63;
                    U32* base = g_kt + ((size_t)((b*16 + h)*32 + (s2>>6)))*4096;
                    int c = s2 & 63, nfk = c >> 3, g = c & 7;
                    int swb = ((g>>2)&1) | ((nfk&1)<<1);
                    {
                        int o = hd >> 3, j = hd & 7, tg = j & 3, w = j >> 2;
                        base[(o*2048 + nfk*256 + g*32
                              + (((tg ^ swb ^ (o&3))<<3)) + w*4) >> 2] = f2tf(fx);
                    }
                    {
                        int hd1 = hd + 1;
                        int o = hd1 >> 3, j = hd1 & 7, tg = j & 3, w = j >> 2;
                        base[(o*2048 + nfk*256 + g*32
                              + (((tg ^ swb ^ (o&3))<<3)) + w*4) >> 2] = f2tf(fy);
                    }
                } else {
                    // V packed: element V[s][hd] -> g_vt B-layout
                    int b = m >> 11, s2 = m & 2047;
                    int h = n >> 6, hd = n & 63;
                    U32* base = g_vt + ((size_t)((b*16 + h)*32 + (s2>>6)))*4096;
                    int c = s2 & 63, ks = c >> 3, j = c & 7, tg = j & 3, w = j >> 2;
                    {
                        int nfv = hd >> 3, g = hd & 7;
                        int swb = ((g>>2)&1) | ((nfv&1)<<1);
                        base[(ks*2048 + nfv*256 + g*32
                              + (((tg ^ swb ^ (ks&3))<<3)) + w*4) >> 2] = f2tf(fx);
                    }
                    {
                        int hd1 = hd + 1;
                        int nfv = hd1 >> 3, g = hd1 & 7;
                        int swb = ((g>>2)&1) | ((nfv&1)<<1);
                        base[(ks*2048 + nfv*256 + g*32
                              + (((tg ^ swb ^ (ks&3))<<3)) + w*4) >> 2] = f2tf(fy);
                    }
                }
            }
        }
    }
}

// ---------------- RoPE table -----------------------------------------------
__global__ void rope_table_kernel()
{
    int idx = blockIdx.x * blockDim.x + threadIdx.x;
    if (idx >= NS*32) return;
    int s = idx >> 5, p = idx & 31;
    double invf = 1.0 / pow(10000.0, (double)(2*p) / 64.0);
    double a = (double)s * invf;
    g_cos[idx] = (float)cos(a);
    g_sin[idx] = (float)sin(a);
}

// ============================================================================
// Flash attention v3 (R11, proven): K/V streamed via cp.async from packed
// g_kt/g_vt, 2-stage double buffer. Tile 64x64, 128 thr = 4 warps.
// Dynamic smem: Ks[2][16KB] + Vs[2][16KB] + Ps[16KB] = 80KB.
// ============================================================================
#define FLS_BYTES (5*16384)

__global__ void __launch_bounds__(128)
flash_mma_kernel()
{
    extern __shared__ __align__(128) char fsm[];
    char* Ks = fsm;                      // 2 stages x 16KB
    char* Vs = fsm + 32768;              // 2 stages x 16KB
    char* Ps = fsm + 65536;              // A-layout P^T; doubles as Q staging

    const int t    = threadIdx.x;
    const int lane = t & 31;
    const int wid  = t >> 5;
    const int grp  = lane >> 2;
    const int tig  = lane & 3;
    const int wr   = wid * 16;
    const int mfW  = wid;
    const int tigA = tig ^ ((grp >> 1) & 3);
    const int bh   = blockIdx.y;
    const int qb   = (int)gridDim.x - 1 - (int)blockIdx.x;  // heavy first
    const int q0   = qb * 64;

    const float* qp = g_q + (size_t)bh * NS * 64;
    const U32* ktp = g_kt + (size_t)bh * 32 * 4096;
    const U32* vtp = g_vt + (size_t)bh * 32 * 4096;
    const U32 sbK = smem_u32(Ks);
    const U32 sbV = smem_u32(Vs);

    auto CPAKV = [&](int kb, int st){
        const U32 dK = sbK + st*16384;
        const U32 dV = sbV + st*16384;
        const U32* sK = ktp + (size_t)kb*4096;
        const U32* sV = vtp + (size_t)kb*4096;
        #pragma unroll
        for (int i = 0; i < 8; ++i) {
            int c = i*128 + t;
            cpa16(dK + c*16, sK + c*4);
            cpa16(dV + c*16, sV + c*4);
        }
        asm volatile("cp.async.commit_group;" ::: "memory");
    };

    // ---- stage Q (scaled) into Ps using A-layout ----
    {
        const int r = t >> 1, ksP = t & 1;
        const int mf = r >> 4, g = r & 7, hi = (r >> 3) & 1;
        const int swz = (g >> 1) & 3;
        const float* pq = qp + (size_t)(q0 + r)*64 + ksP*32;
        char* base = Ps + mf*512 + g*64 + hi*4;
        #pragma unroll
        for (int j8 = 0; j8 < 4; ++j8) {
            float4 f0 = *(const float4*)(pq + j8*8);
            float4 f1 = *(const float4*)(pq + j8*8 + 4);
            int ks = ksP*4 + j8;
            float vals[8] = {f0.x,f0.y,f0.z,f0.w,f1.x,f1.y,f1.z,f1.w};
            #pragma unroll
            for (int j = 0; j < 8; ++j) {
                int tg = j & 3, khi = j >> 2;
                *(U32*)(base + ks*2048 + ((tg^swz)<<4) + khi*8) =
                    f2tf(vals[j] * ATT_SCALE);
            }
        }
    }
    CPAKV(0, 0);                         // prefetch first K/V tile
    __syncthreads();

    // ---- Q fragments -> registers ----
    U32 qf[8][4];
    #pragma unroll
    for (int ks = 0; ks < 8; ++ks)
        *(uint4*)qf[ks] =
            *(const uint4*)(Ps + ks*2048 + mfW*512 + grp*64 + (tigA<<4));

    float m_[2], l_[2];
    m_[0] = m_[1] = -1e30f;
    l_[0] = l_[1] = 0.0f;
    float octx[8][4];
    #pragma unroll
    for (int nf=0;nf<8;++nf)
        #pragma unroll
        for (int r=0;r<4;++r) octx[nf][r] = 0.0f;

    for (int kb = 0; kb <= qb; ++kb) {
        const int st = kb & 1;
        if (kb < qb) CPAKV(kb + 1, (kb + 1) & 1);
        if (kb < qb) asm volatile("cp.async.wait_group 1;" ::: "memory");
        else         asm volatile("cp.async.wait_group 0;" ::: "memory");
        __syncthreads();                 // K/V tile kb ready; Ps safe to reuse

        const int k0 = kb * 64;
        char* Kc = Ks + st*16384;
        char* Vc = Vs + st*16384;

        // ---- S = Q @ K^T ----
        float sacc[8][4];
        #pragma unroll
        for (int nf=0;nf<8;++nf)
            #pragma unroll
            for (int r=0;r<4;++r) sacc[nf][r] = 0.0f;
        #pragma unroll
        for (int ks = 0; ks < 8; ++ks) {
            #pragma unroll
            for (int nf = 0; nf < 8; ++nf) {
                int tb = tig ^ (((grp>>2)&1) | ((nf&1)<<1)) ^ (ks&3);
                uint2 bf = *(const uint2*)(Kc + ks*2048 + nf*256
                                              + grp*32 + (tb<<3));
                mma8(sacc[nf], qf[ks], (const U32*)&bf);
            }
        }

        // ---- online softmax; write P^T in A-layout ----
        const bool diag = (kb == qb);
        #pragma unroll
        for (int l = 0; l < 2; ++l) {
            const int rloc = wr + grp + 8*l;
            const int gi   = q0 + rloc;
            float rm = -1e30f;
            #pragma unroll
            for (int nf = 0; nf < 8; ++nf) {
                #pragma unroll
                for (int c = 0; c < 2; ++c) {
                    float s = sacc[nf][2*l + c];
                    if (diag) {
                        int gj = k0 + nf*8 + 2*tig + c;
                        if (gj >= gi && !(gi == 0 && gj == 0)) s = -1e30f;
                    }
                    sacc[nf][2*l + c] = s;
                    rm = fmaxf(rm, s);
                }
            }
            rm = fmaxf(rm, __shfl_xor_sync(0xffffffffu, rm, 1));
            rm = fmaxf(rm, __shfl_xor_sync(0xffffffffu, rm, 2));
            float mnew = fmaxf(m_[l], rm);
            float fac  = __expf(m_[l] - mnew);
            float ps = 0.0f;
            char* pbase = Ps + mfW*512 + grp*64 + l*4;
            const int swzP = (grp >> 1) & 3;
            #pragma unroll
            for (int nf = 0; nf < 8; ++nf) {
                #pragma unroll
                for (int c = 0; c < 2; ++c) {
                    float p = __expf(sacc[nf][2*l + c] - mnew);
                    int j = 2*tig + c;
                    int tg = j & 3, khi = j >> 2;
                    *(U32*)(pbase + nf*2048 + ((tg^swzP)<<4) + khi*8) = f2tf(p);
                    ps += p;
                }
            }
            ps += __shfl_xor_sync(0xffffffffu, ps, 1);
            ps += __shfl_xor_sync(0xffffffffu, ps, 2);
            l_[l] = l_[l]*fac + ps;
            m_[l] = mnew;
            #pragma unroll
            for (int nf = 0; nf < 8; ++nf) {
                octx[nf][2*l + 0] *= fac;
                octx[nf][2*l + 1] *= fac;
            }
        }
        __syncwarp();                    // P^T region is warp-private

        // ---- ctx += P @ V ----
        #pragma unroll
        for (int ks = 0; ks < 8; ++ks) {
            uint4 af = *(const uint4*)(Ps + ks*2048 + mfW*512
                                          + grp*64 + (tigA<<4));
            #pragma unroll
            for (int nf = 0; nf < 8; ++nf) {
                int tb = tig ^ (((grp>>2)&1) | ((nf&1)<<1)) ^ (ks&3);
                uint2 bf = *(const uint2*)(Vc + ks*2048 + nf*256
                                              + grp*32 + (tb<<3));
                mma8(octx[nf], (const U32*)&af, (const U32*)&bf);
            }
        }
        __syncthreads();                 // all warps done with buffer st
    }

    // ---- normalize + write ctx tf32-rounded (head-major) ----
    U32* op = (U32*)(g_ctx + (size_t)bh * NS * 64);
    #pragma unroll
    for (int l = 0; l < 2; ++l) {
        const int r  = q0 + wr + grp + 8*l;
        const float inv = 1.0f / l_[l];
        #pragma unroll
        for (int nf = 0; nf < 8; ++nf) {
            uint2 u;
            u.x = f2tf(octx[nf][2*l + 0] * inv);
            u.y = f2tf(octx[nf][2*l + 1] * inv);
            *(uint2*)(op + (size_t)r*64 + nf*8 + 2*tig) = u;
        }
    }
}

// ---------------------------------------------------------------------------
extern "C" void kernel_launch(void* const* d_in, const int* in_sizes, int n_in,
                              void* d_out, int out_size)
{
    const float* q  = (const float*)d_in[0];
    const float* k  = (const float*)d_in[1];
    const float* v  = (const float*)d_in[2];
    const float* Wq = (const float*)d_in[3];
    const float* Wk = (const float*)d_in[4];
    const float* Wv = (const float*)d_in[5];
    const float* Wo = (const float*)d_in[6];
    float* out = (float*)d_out;

    float *pq, *pctx;
    cudaGetSymbolAddress((void**)&pq,   g_q);
    cudaGetSymbolAddress((void**)&pctx, g_ctx);
    U32 *pqc, *pkc, *pvc, *pwq, *pwk, *pwv, *pwo;
    cudaGetSymbolAddress((void**)&pqc, g_qc);
    cudaGetSymbolAddress((void**)&pkc, g_kc);
    cudaGetSymbolAddress((void**)&pvc, g_vc);
    cudaGetSymbolAddress((void**)&pwq, g_wqc);
    cudaGetSymbolAddress((void**)&pwk, g_wkc);
    cudaGetSymbolAddress((void**)&pwv, g_wvc);
    cudaGetSymbolAddress((void**)&pwo, g_woc);

    cudaFuncSetAttribute(flash_mma_kernel,
                         cudaFuncAttributeMaxDynamicSharedMemorySize,
                         FLS_BYTES);

    rope_table_kernel<<<256, 256>>>();
    prep_kernel<<<(3*Q4 + 4*W4)/256, 256>>>((const float4*)q, (const float4*)k,
        (const float4*)v, (const float4*)Wq, (const float4*)Wk,
        (const float4*)Wv, (const float4*)Wo);

    dim3 gg(NE/128, NM/128);               // (8, 32)
    gemm_mma<<<gg, 256>>>(pqc, pwq, pq,      0, 1, 1);  // Q proj + RoPE -> head-major
    gemm_mma<<<gg, 256>>>(pkc, pwk, nullptr, 0, 2, 1);  // K proj + RoPE -> packed g_kt
    gemm_mma<<<gg, 256>>>(pvc, pwv, nullptr, 0, 3, 0);  // V proj        -> packed g_vt

    dim3 fg(NS/64, NB*NH);                 // (32, 32)
    flash_mma_kernel<<<fg, 128, FLS_BYTES>>>();

    gemm_mma<<<gg, 256>>>((const U32*)pctx, pwo, out, 1, 0, 0);  // output proj
}

// round 14
// speedup vs baseline: 1.1888x; 1.0865x over previous
#include <cuda_runtime.h>
#include <math.h>

typedef unsigned long long ULL;
typedef unsigned int U32;

#define NB 2
#define NS 2048
#define NE 1024
#define NH 16
#define NHD 64
#define NM 4096                  // NB*NS
#define ATT_SCALE (1.0f/32.0f)   // 1/sqrt(1024), exact power of two

// ---------------- scratch (device globals; no allocation allowed) ----------
__device__ float g_q[NB*NH*NS*NHD];    // head-major: [b*16+h][s][hd]
__device__ float g_ctx[NB*NH*NS*NHD];  // written tf32-rounded by flash
__device__ float g_cos[NS*32];
__device__ float g_sin[NS*32];
// pre-converted tf32-bit operands
__device__ U32 g_qc[NM*NE];
__device__ U32 g_kc[NM*NE];
__device__ U32 g_vc[NM*NE];
__device__ U32 g_wqc[NE*NE];
__device__ U32 g_wkc[NE*NE];
__device__ U32 g_wvc[NE*NE];
__device__ U32 g_woc[NE*NE];
// K/V packed into flash B-layout smem images: [bh][kb][4096 U32]
__device__ U32 g_kt[NB*NH*32*4096];
__device__ U32 g_vt[NB*NH*32*4096];

// ---------------- helpers ---------------------------------------------------
__device__ __forceinline__ U32 f2tf(float x){
    U32 u; asm("cvt.rn.tf32.f32 %0, %1;" : "=r"(u) : "f"(x)); return u;
}
__device__ __forceinline__ void mma8(float* c, const U32* a, const U32* b){
    asm volatile("mma.sync.aligned.m16n8k8.row.col.f32.tf32.tf32.f32 "
        "{%0,%1,%2,%3}, {%4,%5,%6,%7}, {%8,%9}, {%0,%1,%2,%3};"
        : "+f"(c[0]), "+f"(c[1]), "+f"(c[2]), "+f"(c[3])
        : "r"(a[0]), "r"(a[1]), "r"(a[2]), "r"(a[3]), "r"(b[0]), "r"(b[1]));
}
__device__ __forceinline__ U32 smem_u32(const void* p){
    U32 a;
    asm("{ .reg .u64 t; cvta.to.shared.u64 t, %1; cvt.u32.u64 %0, t; }"
        : "=r"(a) : "l"(p));
    return a;
}
__device__ __forceinline__ void ldsm4(U32* r, U32 a){
    asm volatile("ldmatrix.sync.aligned.m8n8.x4.shared.b16 {%0,%1,%2,%3}, [%4];"
        : "=r"(r[0]), "=r"(r[1]), "=r"(r[2]), "=r"(r[3]) : "r"(a));
}
__device__ __forceinline__ void ldsm2(U32* r, U32 a){
    asm volatile("ldmatrix.sync.aligned.m8n8.x2.shared.b16 {%0,%1}, [%2];"
        : "=r"(r[0]), "=r"(r[1]) : "r"(a));
}
__device__ __forceinline__ void cpa16(U32 dst, const void* src){
    asm volatile("cp.async.cg.shared.global [%0], [%1], 16;"
                 :: "r"(dst), "l"(src) : "memory");
}

// ---------------- prep: fp32 -> tf32 bits (RN) ------------------------------
#define Q4 (NM*NE/4)
#define W4 (NE*NE/4)
__global__ void prep_kernel(const float4* __restrict__ q, const float4* __restrict__ k,
                            const float4* __restrict__ v, const float4* __restrict__ wq,
                            const float4* __restrict__ wk, const float4* __restrict__ wv,
                            const float4* __restrict__ wo)
{
    int i = blockIdx.x * blockDim.x + threadIdx.x;
    const float4* s; uint4* d;
    if      (i <   Q4) { s = q + i;        d = (uint4*)g_qc + i; }
    else if (i < 2*Q4) { s = k + (i-Q4);   d = (uint4*)g_kc + (i-Q4); }
    else if (i < 3*Q4) { s = v + (i-2*Q4); d = (uint4*)g_vc + (i-2*Q4); }
    else {
        int j = i - 3*Q4, w = j / W4, o = j - w*W4;
        const float4* ws[4] = {wq, wk, wv, wo};
        uint4* wd[4] = {(uint4*)g_wqc, (uint4*)g_wkc, (uint4*)g_wvc, (uint4*)g_woc};
        s = ws[w] + o; d = wd[w] + o;
    }
    float4 f = *s;
    *d = make_uint4(f2tf(f.x), f2tf(f.y), f2tf(f.z), f2tf(f.w));
}

// ============================================================================
// Projection GEMM body (R10/R13, proven): cp.async 3-stage + ldmatrix, BK=16.
// 256 thr = 8 warps (2x4), warp tile 64x32. Static smem 48KB.
// Epilogue modes: 0=plain C [m][n]; 1=head-major fp32 (Q);
//                 2=K packed into g_kt; 3=V packed into g_vt.
// ============================================================================
#define PST 16384

__device__ __forceinline__ void gemm_body(
    const U32* __restrict__ A, const U32* __restrict__ Wt,
    float* __restrict__ C, int a_heads, int mode, int do_rope)
{
    __shared__ __align__(128) char smem[3*PST];
    const U32 sb0 = smem_u32(smem);
    const int t    = threadIdx.x;
    const int lane = t & 31;
    const int wid  = t >> 5;
    const int grp  = lane >> 2;
    const int tig  = lane & 3;
    const int wm   = (wid & 1) * 64;
    const int wn   = (wid >> 1) * 32;
    const int bm   = blockIdx.y * 128;
    const int bn   = blockIdx.x * 128;

    const int prA = t >> 1, prH = t & 1;
    const U32 dsw0 = prA*64 + (((2*prH    ) ^ ((prA>>1)&3)) << 4);
    const U32 dsw1 = prA*64 + (((2*prH + 1) ^ ((prA>>1)&3)) << 4);

    const int rlA = (lane & 7) | (((lane >> 3) & 1) << 3);
    const int cbA = (lane >> 4) & 1;
    const U32 offA = sb0 + (wm + rlA)*64 + ((cbA ^ ((rlA>>1)&3)) << 4);
    const int rlB = lane & 7;
    const int cbB = (lane >> 3) & 1;
    const U32 offB = sb0 + 8192 + (wn + rlB)*64 + ((cbB ^ ((rlB>>1)&3)) << 4);

    float acc[4][4][4];
    #pragma unroll
    for (int i=0;i<4;++i)
        #pragma unroll
        for (int j=0;j<4;++j)
            #pragma unroll
            for (int r=0;r<4;++r) acc[i][j][r] = 0.0f;

    auto CPA = [&](int kt, int st){
        const U32 sA = sb0 + st*PST;
        const U32 sB = sA + 8192;
        const int e0 = kt*16 + prH*8;
        const U32* pa;
        if (!a_heads) pa = A + (size_t)(bm + prA)*NE + e0;
        else {
            int m = bm + prA, b = m >> 11, s = m & 2047;
            pa = A + ((size_t)((b*16 + (e0 >> 6))*NS + s))*64 + (e0 & 63);
        }
        const U32* pb = Wt + (size_t)(bn + prA)*NE + e0;
        cpa16(sA + dsw0, pa);     cpa16(sA + dsw1, pa + 4);
        cpa16(sB + dsw0, pb);     cpa16(sB + dsw1, pb + 4);
        asm volatile("cp.async.commit_group;" ::: "memory");
    };

    auto MMA = [&](int st){
        const U32 bA = offA + st*PST;
        const U32 bB = offB + st*PST;
        #pragma unroll
        for (int ks = 0; ks < 2; ++ks) {
            U32 af[4][4];
            #pragma unroll
            for (int mf = 0; mf < 4; ++mf)
                ldsm4(af[mf], (bA + mf*1024) ^ (ks << 5));
            U32 bf[4][2];
            #pragma unroll
            for (int nf = 0; nf < 4; ++nf)
                ldsm2(bf[nf], (bB + nf*512) ^ (ks << 5));
            #pragma unroll
            for (int mf = 0; mf < 4; ++mf)
                #pragma unroll
                for (int nf = 0; nf < 4; ++nf)
                    mma8(acc[mf][nf], af[mf], bf[nf]);
        }
    };

    CPA(0, 0); CPA(1, 1);
    for (int kt = 0; kt < 64; ++kt) {
        if (kt < 63) asm volatile("cp.async.wait_group 1;" ::: "memory");
        else         asm volatile("cp.async.wait_group 0;" ::: "memory");
        __syncthreads();
        if (kt < 62) CPA(kt + 2, (kt + 2) % 3);
        MMA(kt % 3);
    }

    // epilogue (+ optional fused RoPE: (fx,fy) = one (even,odd) hd pair)
    #pragma unroll
    for (int mf = 0; mf < 4; ++mf) {
        #pragma unroll
        for (int half = 0; half < 2; ++half) {
            int m = bm + wm + mf*16 + grp + half*8;
            #pragma unroll
            for (int nf = 0; nf < 4; ++nf) {
                int n = bn + wn + nf*8 + 2*tig;
                float fx = acc[mf][nf][half*2 + 0];
                float fy = acc[mf][nf][half*2 + 1];
                if (do_rope) {
                    int s = m & 2047;
                    int p = (n & 63) >> 1;
                    float co = g_cos[s*32 + p], sn = g_sin[s*32 + p];
                    float rx = fx*co - fy*sn;
                    float ry = fx*sn + fy*co;
                    fx = rx; fy = ry;
                }
                if (mode == 0) {
                    *(float2*)(C + (size_t)m*NE + n) = make_float2(fx, fy);
                } else if (mode == 1) {
                    int b = m >> 11, s2 = m & 2047;
                    *(float2*)(C + ((size_t)((b*16 + (n>>6))*NS + s2))*64 + (n & 63))
                        = make_float2(fx, fy);
                } else if (mode == 2) {
                    // K packed: element K[s][hd] -> g_kt B-layout
                    int b = m >> 11, s2 = m & 2047;
                    int h = n >> 6, hd = n & 63;
                    U32* base = g_kt + ((size_t)((b*16 + h)*32 + (s2>>6)))*4096;
                    int c = s2 & 63, nfk = c >> 3, g = c & 7;
                    int swb = ((g>>2)&1) | ((nfk&1)<<1);
                    {
                        int o = hd >> 3, j = hd & 7, tg = j & 3, w = j >> 2;
                        base[(o*2048 + nfk*256 + g*32
                              + (((tg ^ swb ^ (o&3))<<3)) + w*4) >> 2] = f2tf(fx);
                    }
                    {
                        int hd1 = hd + 1;
                        int o = hd1 >> 3, j = hd1 & 7, tg = j & 3, w = j >> 2;
                        base[(o*2048 + nfk*256 + g*32
                              + (((tg ^ swb ^ (o&3))<<3)) + w*4) >> 2] = f2tf(fy);
                    }
                } else {
                    // V packed: element V[s][hd] -> g_vt B-layout
                    int b = m >> 11, s2 = m & 2047;
                    int h = n >> 6, hd = n & 63;
                    U32* base = g_vt + ((size_t)((b*16 + h)*32 + (s2>>6)))*4096;
                    int c = s2 & 63, ks = c >> 3, j = c & 7, tg = j & 3, w = j >> 2;
                    {
                        int nfv = hd >> 3, g = hd & 7;
                        int swb = ((g>>2)&1) | ((nfv&1)<<1);
                        base[(ks*2048 + nfv*256 + g*32
                              + (((tg ^ swb ^ (ks&3))<<3)) + w*4) >> 2] = f2tf(fx);
                    }
                    {
                        int hd1 = hd + 1;
                        int nfv = hd1 >> 3, g = hd1 & 7;
                        int swb = ((g>>2)&1) | ((nfv&1)<<1);
                        base[(ks*2048 + nfv*256 + g*32
                              + (((tg ^ swb ^ (ks&3))<<3)) + w*4) >> 2] = f2tf(fy);
                    }
                }
            }
        }
    }
}

// combined QKV launch: blockIdx.z selects projection
__global__ void __launch_bounds__(256, 2)
qkv_mma()
{
    const int z = blockIdx.z;
    const U32* A = (z == 0) ? g_qc : (z == 1) ? g_kc : g_vc;
    const U32* W = (z == 0) ? g_wqc : (z == 1) ? g_wkc : g_wvc;
    gemm_body(A, W, g_q, 0, z + 1, (z < 2) ? 1 : 0);
}

__global__ void __launch_bounds__(256, 2)
gemm_mma(const U32* __restrict__ A, const U32* __restrict__ Wt,
         float* __restrict__ C, int a_heads, int mode, int do_rope)
{
    gemm_body(A, Wt, C, a_heads, mode, do_rope);
}

// ---------------- RoPE table -----------------------------------------------
__global__ void rope_table_kernel()
{
    int idx = blockIdx.x * blockDim.x + threadIdx.x;
    if (idx >= NS*32) return;
    int s = idx >> 5, p = idx & 31;
    double invf = 1.0 / pow(10000.0, (double)(2*p) / 64.0);
    double a = (double)s * invf;
    g_cos[idx] = (float)cos(a);
    g_sin[idx] = (float)sin(a);
}

// ============================================================================
// Flash attention v5: Ks double-buffered, Vs SINGLE buffer (waited after
// softmax), Ps. Smem 64KB -> 3 CTAs/SM. Tile 64x64, 128 thr = 4 warps.
// ============================================================================
#define FLS_BYTES (4*16384)      // Ks[2] 32KB + Vs 16KB + Ps 16KB

__global__ void __launch_bounds__(128, 3)
flash_mma_kernel()
{
    extern __shared__ __align__(128) char fsm[];
    char* Ks = fsm;                      // 2 stages x 16KB
    char* Vs = fsm + 32768;              // 1 stage  x 16KB
    char* Ps = fsm + 49152;              // A-layout P^T; doubles as Q staging

    const int t    = threadIdx.x;
    const int lane = t & 31;
    const int wid  = t >> 5;
    const int grp  = lane >> 2;
    const int tig  = lane & 3;
    const int wr   = wid * 16;
    const int mfW  = wid;
    const int tigA = tig ^ ((grp >> 1) & 3);
    const int bh   = blockIdx.y;
    const int qb   = (int)gridDim.x - 1 - (int)blockIdx.x;  // heavy first
    const int q0   = qb * 64;

    const float* qp = g_q + (size_t)bh * NS * 64;
    const U32* ktp = g_kt + (size_t)bh * 32 * 4096;
    const U32* vtp = g_vt + (size_t)bh * 32 * 4096;
    const U32 sbK = smem_u32(Ks);
    const U32 sbV = smem_u32(Vs);

    auto CPAK = [&](int kb, int st){
        const U32 dK = sbK + st*16384;
        const U32* sK = ktp + (size_t)kb*4096;
        #pragma unroll
        for (int i = 0; i < 8; ++i) {
            int c = i*128 + t;
            cpa16(dK + c*16, sK + c*4);
        }
        asm volatile("cp.async.commit_group;" ::: "memory");
    };
    auto CPAV = [&](int kb){
        const U32* sV = vtp + (size_t)kb*4096;
        #pragma unroll
        for (int i = 0; i < 8; ++i) {
            int c = i*128 + t;
            cpa16(sbV + c*16, sV + c*4);
        }
        asm volatile("cp.async.commit_group;" ::: "memory");
    };

    // ---- stage Q (scaled) into Ps using A-layout ----
    {
        const int r = t >> 1, ksP = t & 1;
        const int mf = r >> 4, g = r & 7, hi = (r >> 3) & 1;
        const int swz = (g >> 1) & 3;
        const float* pq = qp + (size_t)(q0 + r)*64 + ksP*32;
        char* base = Ps + mf*512 + g*64 + hi*4;
        #pragma unroll
        for (int j8 = 0; j8 < 4; ++j8) {
            float4 f0 = *(const float4*)(pq + j8*8);
            float4 f1 = *(const float4*)(pq + j8*8 + 4);
            int ks = ksP*4 + j8;
            float vals[8] = {f0.x,f0.y,f0.z,f0.w,f1.x,f1.y,f1.z,f1.w};
            #pragma unroll
            for (int j = 0; j < 8; ++j) {
                int tg = j & 3, khi = j >> 2;
                *(U32*)(base + ks*2048 + ((tg^swz)<<4) + khi*8) =
                    f2tf(vals[j] * ATT_SCALE);
            }
        }
    }
    CPAK(0, 0);                          // prefetch first K tile
    __syncthreads();

    // ---- Q fragments -> registers ----
    U32 qf[8][4];
    #pragma unroll
    for (int ks = 0; ks < 8; ++ks)
        *(uint4*)qf[ks] =
            *(const uint4*)(Ps + ks*2048 + mfW*512 + grp*64 + (tigA<<4));

    float m_[2], l_[2];
    m_[0] = m_[1] = -1e30f;
    l_[0] = l_[1] = 0.0f;
    float octx[8][4];
    #pragma unroll
    for (int nf=0;nf<8;++nf)
        #pragma unroll
        for (int r=0;r<4;++r) octx[nf][r] = 0.0f;

    for (int kb = 0; kb <= qb; ++kb) {
        const int st = kb & 1;
        CPAV(kb);                        // V for this iter (waited post-softmax)
        if (kb < qb) CPAK(kb + 1, st ^ 1);
        // wait for K(kb): pending = {K(kb), V(kb)[, K(kb+1)]}
        if (kb < qb) asm volatile("cp.async.wait_group 2;" ::: "memory");
        else         asm volatile("cp.async.wait_group 1;" ::: "memory");
        __syncthreads();

        const int k0 = kb * 64;
        char* Kc = Ks + st*16384;

        // ---- S = Q @ K^T ----
        float sacc[8][4];
        #pragma unroll
        for (int nf=0;nf<8;++nf)
            #pragma unroll
            for (int r=0;r<4;++r) sacc[nf][r] = 0.0f;
        #pragma unroll
        for (int ks = 0; ks < 8; ++ks) {
            #pragma unroll
            for (int nf = 0; nf < 8; ++nf) {
                int tb = tig ^ (((grp>>2)&1) | ((nf&1)<<1)) ^ (ks&3);
                uint2 bf = *(const uint2*)(Kc + ks*2048 + nf*256
                                              + grp*32 + (tb<<3));
                mma8(sacc[nf], qf[ks], (const U32*)&bf);
            }
        }

        // ---- online softmax; write P^T in A-layout ----
        const bool diag = (kb == qb);
        #pragma unroll
        for (int l = 0; l < 2; ++l) {
            const int rloc = wr + grp + 8*l;
            const int gi   = q0 + rloc;
            float rm = -1e30f;
            #pragma unroll
            for (int nf = 0; nf < 8; ++nf) {
                #pragma unroll
                for (int c = 0; c < 2; ++c) {
                    float s = sacc[nf][2*l + c];
                    if (diag) {
                        int gj = k0 + nf*8 + 2*tig + c;
                        if (gj >= gi && !(gi == 0 && gj == 0)) s = -1e30f;
                    }
                    sacc[nf][2*l + c] = s;
                    rm = fmaxf(rm, s);
                }
            }
            rm = fmaxf(rm, __shfl_xor_sync(0xffffffffu, rm, 1));
            rm = fmaxf(rm, __shfl_xor_sync(0xffffffffu, rm, 2));
            float mnew = fmaxf(m_[l], rm);
            float fac  = __expf(m_[l] - mnew);
            float ps = 0.0f;
            char* pbase = Ps + mfW*512 + grp*64 + l*4;
            const int swzP = (grp >> 1) & 3;
            #pragma unroll
            for (int nf = 0; nf < 8; ++nf) {
                #pragma unroll
                for (int c = 0; c < 2; ++c) {
                    float p = __expf(sacc[nf][2*l + c] - mnew);
                    int j = 2*tig + c;
                    int tg = j & 3, khi = j >> 2;
                    *(U32*)(pbase + nf*2048 + ((tg^swzP)<<4) + khi*8) = f2tf(p);
                    ps += p;
                }
            }
            ps += __shfl_xor_sync(0xffffffffu, ps, 1);
            ps += __shfl_xor_sync(0xffffffffu, ps, 2);
            l_[l] = l_[l]*fac + ps;
            m_[l] = mnew;
            #pragma unroll
            for (int nf = 0; nf < 8; ++nf) {
                octx[nf][2*l + 0] *= fac;
                octx[nf][2*l + 1] *= fac;
            }
        }

        // ---- wait for V(kb): pending = {V(kb)[, K(kb+1)]} ----
        if (kb < qb) asm volatile("cp.async.wait_group 1;" ::: "memory");
        else         asm volatile("cp.async.wait_group 0;" ::: "memory");
        __syncthreads();                 // V visible to all; also orders Ps

        // ---- ctx += P @ V ----
        #pragma unroll
        for (int ks = 0; ks < 8; ++ks) {
            uint4 af = *(const uint4*)(Ps + ks*2048 + mfW*512
                                          + grp*64 + (tigA<<4));
            #pragma unroll
            for (int nf = 0; nf < 8; ++nf) {
                int tb = tig ^ (((grp>>2)&1) | ((nf&1)<<1)) ^ (ks&3);
                uint2 bf = *(const uint2*)(Vs + ks*2048 + nf*256
                                              + grp*32 + (tb<<3));
                mma8(octx[nf], (const U32*)&af, (const U32*)&bf);
            }
        }
        __syncthreads();                 // Vs safe for next iter's CPAV
    }

    // ---- normalize + write ctx tf32-rounded (head-major) ----
    U32* op = (U32*)(g_ctx + (size_t)bh * NS * 64);
    #pragma unroll
    for (int l = 0; l < 2; ++l) {
        const int r  = q0 + wr + grp + 8*l;
        const float inv = 1.0f / l_[l];
        #pragma unroll
        for (int nf = 0; nf < 8; ++nf) {
            uint2 u;
            u.x = f2tf(octx[nf][2*l + 0] * inv);
            u.y = f2tf(octx[nf][2*l + 1] * inv);
            *(uint2*)(op + (size_t)r*64 + nf*8 + 2*tig) = u;
        }
    }
}

// ---------------------------------------------------------------------------
extern "C" void kernel_launch(void* const* d_in, const int* in_sizes, int n_in,
                              void* d_out, int out_size)
{
    const float* q  = (const float*)d_in[0];
    const float* k  = (const float*)d_in[1];
    const float* v  = (const float*)d_in[2];
    const float* Wq = (const float*)d_in[3];
    const float* Wk = (const float*)d_in[4];
    const float* Wv = (const float*)d_in[5];
    const float* Wo = (const float*)d_in[6];
    float* out = (float*)d_out;

    float *pctx;
    cudaGetSymbolAddress((void**)&pctx, g_ctx);
    U32 *pwo;
    cudaGetSymbolAddress((void**)&pwo, g_woc);

    cudaFuncSetAttribute(flash_mma_kernel,
                         cudaFuncAttributeMaxDynamicSharedMemorySize,
                         FLS_BYTES);

    rope_table_kernel<<<256, 256>>>();
    prep_kernel<<<(3*Q4 + 4*W4)/256, 256>>>((const float4*)q, (const float4*)k,
        (const float4*)v, (const float4*)Wq, (const float4*)Wk,
        (const float4*)Wv, (const float4*)Wo);

    dim3 gq(NE/128, NM/128, 3);            // (8, 32, 3): Q,K,V in one launch
    qkv_mma<<<gq, 256>>>();

    dim3 fg(NS/64, NB*NH);                 // (32, 32)
    flash_mma_kernel<<<fg, 128, FLS_BYTES>>>();

    dim3 gg(NE/128, NM/128);               // (8, 32)
    gemm_mma<<<gg, 256>>>((const U32*)pctx, pwo, out, 1, 0, 0);  // output proj
}

// round 15
// speedup vs baseline: 1.2076x; 1.0159x over previous
#include <cuda_runtime.h>
#include <math.h>

typedef unsigned long long ULL;
typedef unsigned int U32;

#define NB 2
#define NS 2048
#define NE 1024
#define NH 16
#define NHD 64
#define NM 4096                  // NB*NS
#define ATT_SCALE (1.0f/32.0f)   // 1/sqrt(1024), exact power of two

// ---------------- scratch (device globals; no allocation allowed) ----------
__device__ float g_q[NB*NH*NS*NHD];    // head-major: [b*16+h][s][hd]
__device__ float g_ctx[NB*NH*NS*NHD];  // written tf32-rounded by flash
__device__ float g_cos[NS*32];
__device__ float g_sin[NS*32];
// pre-converted tf32-bit operands
__device__ U32 g_qc[NM*NE];
__device__ U32 g_kc[NM*NE];
__device__ U32 g_vc[NM*NE];
__device__ U32 g_wqc[NE*NE];
__device__ U32 g_wkc[NE*NE];
__device__ U32 g_wvc[NE*NE];
__device__ U32 g_woc[NE*NE];
// K/V packed into flash paired-b-frag images: [bh][kb][4096 U32]
// word = ks*512 + nfp*128 + g*16 + tg*4 + nlo*2 + w
//   K: (n=kv col c: nfp=c>>4, nlo=(c>>3)&1, g=c&7), (k=hd: ks=hd>>3, tg=hd&3, w=(hd>>2)&1)
//   V: (n=hd), (k=kv col within tile)
__device__ U32 g_kt[NB*NH*32*4096];
__device__ U32 g_vt[NB*NH*32*4096];

// ---------------- helpers ---------------------------------------------------
__device__ __forceinline__ U32 f2tf(float x){
    U32 u; asm("cvt.rn.tf32.f32 %0, %1;" : "=r"(u) : "f"(x)); return u;
}
__device__ __forceinline__ void mma8(float* c, const U32* a, const U32* b){
    asm volatile("mma.sync.aligned.m16n8k8.row.col.f32.tf32.tf32.f32 "
        "{%0,%1,%2,%3}, {%4,%5,%6,%7}, {%8,%9}, {%0,%1,%2,%3};"
        : "+f"(c[0]), "+f"(c[1]), "+f"(c[2]), "+f"(c[3])
        : "r"(a[0]), "r"(a[1]), "r"(a[2]), "r"(a[3]), "r"(b[0]), "r"(b[1]));
}
__device__ __forceinline__ U32 smem_u32(const void* p){
    U32 a;
    asm("{ .reg .u64 t; cvta.to.shared.u64 t, %1; cvt.u32.u64 %0, t; }"
        : "=r"(a) : "l"(p));
    return a;
}
__device__ __forceinline__ void ldsm4(U32* r, U32 a){
    asm volatile("ldmatrix.sync.aligned.m8n8.x4.shared.b16 {%0,%1,%2,%3}, [%4];"
        : "=r"(r[0]), "=r"(r[1]), "=r"(r[2]), "=r"(r[3]) : "r"(a));
}
__device__ __forceinline__ void ldsm2(U32* r, U32 a){
    asm volatile("ldmatrix.sync.aligned.m8n8.x2.shared.b16 {%0,%1}, [%2];"
        : "=r"(r[0]), "=r"(r[1]) : "r"(a));
}
__device__ __forceinline__ void cpa16(U32 dst, const void* src){
    asm volatile("cp.async.cg.shared.global [%0], [%1], 16;"
                 :: "r"(dst), "l"(src) : "memory");
}

// ---------------- prep: fp32 -> tf32 bits (RN) ------------------------------
#define Q4 (NM*NE/4)
#define W4 (NE*NE/4)
__global__ void prep_kernel(const float4* __restrict__ q, const float4* __restrict__ k,
                            const float4* __restrict__ v, const float4* __restrict__ wq,
                            const float4* __restrict__ wk, const float4* __restrict__ wv,
                            const float4* __restrict__ wo)
{
    int i = blockIdx.x * blockDim.x + threadIdx.x;
    const float4* s; uint4* d;
    if      (i <   Q4) { s = q + i;        d = (uint4*)g_qc + i; }
    else if (i < 2*Q4) { s = k + (i-Q4);   d = (uint4*)g_kc + (i-Q4); }
    else if (i < 3*Q4) { s = v + (i-2*Q4); d = (uint4*)g_vc + (i-2*Q4); }
    else {
        int j = i - 3*Q4, w = j / W4, o = j - w*W4;
        const float4* ws[4] = {wq, wk, wv, wo};
        uint4* wd[4] = {(uint4*)g_wqc, (uint4*)g_wkc, (uint4*)g_wvc, (uint4*)g_woc};
        s = ws[w] + o; d = wd[w] + o;
    }
    float4 f = *s;
    *d = make_uint4(f2tf(f.x), f2tf(f.y), f2tf(f.z), f2tf(f.w));
}

// ============================================================================
// Projection GEMM body (proven): cp.async 3-stage + ldmatrix, BK=16.
// 256 thr = 8 warps (2x4), warp tile 64x32. Static smem 48KB.
// Epilogue modes: 0=plain C [m][n]; 1=head-major fp32 (Q);
//                 2=K packed into g_kt; 3=V packed into g_vt.
// ============================================================================
#define PST 16384

__device__ __forceinline__ void gemm_body(
    const U32* __restrict__ A, const U32* __restrict__ Wt,
    float* __restrict__ C, int a_heads, int mode, int do_rope)
{
    __shared__ __align__(128) char smem[3*PST];
    const U32 sb0 = smem_u32(smem);
    const int t    = threadIdx.x;
    const int lane = t & 31;
    const int wid  = t >> 5;
    const int grp  = lane >> 2;
    const int tig  = lane & 3;
    const int wm   = (wid & 1) * 64;
    const int wn   = (wid >> 1) * 32;
    const int bm   = blockIdx.y * 128;
    const int bn   = blockIdx.x * 128;

    const int prA = t >> 1, prH = t & 1;
    const U32 dsw0 = prA*64 + (((2*prH    ) ^ ((prA>>1)&3)) << 4);
    const U32 dsw1 = prA*64 + (((2*prH + 1) ^ ((prA>>1)&3)) << 4);

    const int rlA = (lane & 7) | (((lane >> 3) & 1) << 3);
    const int cbA = (lane >> 4) & 1;
    const U32 offA = sb0 + (wm + rlA)*64 + ((cbA ^ ((rlA>>1)&3)) << 4);
    const int rlB = lane & 7;
    const int cbB = (lane >> 3) & 1;
    const U32 offB = sb0 + 8192 + (wn + rlB)*64 + ((cbB ^ ((rlB>>1)&3)) << 4);

    float acc[4][4][4];
    #pragma unroll
    for (int i=0;i<4;++i)
        #pragma unroll
        for (int j=0;j<4;++j)
            #pragma unroll
            for (int r=0;r<4;++r) acc[i][j][r] = 0.0f;

    auto CPA = [&](int kt, int st){
        const U32 sA = sb0 + st*PST;
        const U32 sB = sA + 8192;
        const int e0 = kt*16 + prH*8;
        const U32* pa;
        if (!a_heads) pa = A + (size_t)(bm + prA)*NE + e0;
        else {
            int m = bm + prA, b = m >> 11, s = m & 2047;
            pa = A + ((size_t)((b*16 + (e0 >> 6))*NS + s))*64 + (e0 & 63);
        }
        const U32* pb = Wt + (size_t)(bn + prA)*NE + e0;
        cpa16(sA + dsw0, pa);     cpa16(sA + dsw1, pa + 4);
        cpa16(sB + dsw0, pb);     cpa16(sB + dsw1, pb + 4);
        asm volatile("cp.async.commit_group;" ::: "memory");
    };

    auto MMA = [&](int st){
        const U32 bA = offA + st*PST;
        const U32 bB = offB + st*PST;
        #pragma unroll
        for (int ks = 0; ks < 2; ++ks) {
            U32 af[4][4];
            #pragma unroll
            for (int mf = 0; mf < 4; ++mf)
                ldsm4(af[mf], (bA + mf*1024) ^ (ks << 5));
            U32 bf[4][2];
            #pragma unroll
            for (int nf = 0; nf < 4; ++nf)
                ldsm2(bf[nf], (bB + nf*512) ^ (ks << 5));
            #pragma unroll
            for (int mf = 0; mf < 4; ++mf)
                #pragma unroll
                for (int nf = 0; nf < 4; ++nf)
                    mma8(acc[mf][nf], af[mf], bf[nf]);
        }
    };

    CPA(0, 0); CPA(1, 1);
    for (int kt = 0; kt < 64; ++kt) {
        if (kt < 63) asm volatile("cp.async.wait_group 1;" ::: "memory");
        else         asm volatile("cp.async.wait_group 0;" ::: "memory");
        __syncthreads();
        if (kt < 62) CPA(kt + 2, (kt + 2) % 3);
        MMA(kt % 3);
    }

    // epilogue (+ optional fused RoPE: (fx,fy) = one (even,odd) hd pair)
    #pragma unroll
    for (int mf = 0; mf < 4; ++mf) {
        #pragma unroll
        for (int half = 0; half < 2; ++half) {
            int m = bm + wm + mf*16 + grp + half*8;
            #pragma unroll
            for (int nf = 0; nf < 4; ++nf) {
                int n = bn + wn + nf*8 + 2*tig;
                float fx = acc[mf][nf][half*2 + 0];
                float fy = acc[mf][nf][half*2 + 1];
                if (do_rope) {
                    int s = m & 2047;
                    int p = (n & 63) >> 1;
                    float co = g_cos[s*32 + p], sn = g_sin[s*32 + p];
                    float rx = fx*co - fy*sn;
                    float ry = fx*sn + fy*co;
                    fx = rx; fy = ry;
                }
                if (mode == 0) {
                    *(float2*)(C + (size_t)m*NE + n) = make_float2(fx, fy);
                } else if (mode == 1) {
                    int b = m >> 11, s2 = m & 2047;
                    *(float2*)(C + ((size_t)((b*16 + (n>>6))*NS + s2))*64 + (n & 63))
                        = make_float2(fx, fy);
                } else if (mode == 2) {
                    // K packed: element K[s][hd] -> paired-b-frag layout
                    int b = m >> 11, s2 = m & 2047;
                    int h = n >> 6, hd = n & 63;
                    U32* base = g_kt + ((size_t)((b*16 + h)*32 + (s2>>6)))*4096;
                    int c = s2 & 63;
                    int wb = (c>>4)*128 + (c&7)*16 + ((c>>3)&1)*2;
                    {
                        int ks = hd >> 3, j = hd & 7;
                        base[ks*512 + wb + (j&3)*4 + (j>>2)] = f2tf(fx);
                    }
                    {
                        int hd1 = hd + 1;
                        int ks = hd1 >> 3, j = hd1 & 7;
                        base[ks*512 + wb + (j&3)*4 + (j>>2)] = f2tf(fy);
                    }
                } else {
                    // V packed: element V[s][hd] -> paired-b-frag layout
                    int b = m >> 11, s2 = m & 2047;
                    int h = n >> 6, hd = n & 63;
                    U32* base = g_vt + ((size_t)((b*16 + h)*32 + (s2>>6)))*4096;
                    int c = s2 & 63, j = c & 7;
                    int kofs = (c>>3)*512 + (j&3)*4 + (j>>2);
                    base[kofs + (hd>>4)*128 + (hd&7)*16 + ((hd>>3)&1)*2] = f2tf(fx);
                    int hd1 = hd + 1;
                    base[kofs + (hd1>>4)*128 + (hd1&7)*16 + ((hd1>>3)&1)*2] = f2tf(fy);
                }
            }
        }
    }
}

// combined QKV launch: blockIdx.z selects projection
__global__ void __launch_bounds__(256, 2)
qkv_mma()
{
    const int z = blockIdx.z;
    const U32* A = (z == 0) ? g_qc : (z == 1) ? g_kc : g_vc;
    const U32* W = (z == 0) ? g_wqc : (z == 1) ? g_wkc : g_wvc;
    gemm_body(A, W, g_q, 0, z + 1, (z < 2) ? 1 : 0);
}

__global__ void __launch_bounds__(256, 2)
gemm_mma(const U32* __restrict__ A, const U32* __restrict__ Wt,
         float* __restrict__ C, int a_heads, int mode, int do_rope)
{
    gemm_body(A, Wt, C, a_heads, mode, do_rope);
}

// ---------------- RoPE table -----------------------------------------------
__global__ void rope_table_kernel()
{
    int idx = blockIdx.x * blockDim.x + threadIdx.x;
    if (idx >= NS*32) return;
    int s = idx >> 5, p = idx & 31;
    double invf = 1.0 / pow(10000.0, (double)(2*p) / 64.0);
    double a = (double)s * invf;
    g_cos[idx] = (float)cos(a);
    g_sin[idx] = (float)sin(a);
}

// ============================================================================
// Flash attention v6: paired-b-frag K/V layout (LDS.128, immediate offsets,
// zero address math). Ks double-buffered, Vs single buffer, Ps. 64KB smem ->
// 3 CTAs/SM. Tile 64x64, 128 thr = 4 warps.
// ============================================================================
#define FLS_BYTES (4*16384)      // Ks[2] 32KB + Vs 16KB + Ps 16KB

__global__ void __launch_bounds__(128, 3)
flash_mma_kernel()
{
    extern __shared__ __align__(128) char fsm[];
    char* Ks = fsm;                      // 2 stages x 16KB
    char* Vs = fsm + 32768;              // 1 stage  x 16KB
    char* Ps = fsm + 49152;              // A-layout P^T; doubles as Q staging

    const int t    = threadIdx.x;
    const int lane = t & 31;
    const int wid  = t >> 5;
    const int grp  = lane >> 2;
    const int tig  = lane & 3;
    const int wr   = wid * 16;
    const int mfW  = wid;
    const int tigA = tig ^ ((grp >> 1) & 3);
    const int bh   = blockIdx.y;
    const int qb   = (int)gridDim.x - 1 - (int)blockIdx.x;  // heavy first
    const int q0   = qb * 64;
    const U32 bco  = (U32)(grp*64 + tig*16);   // b-frag byte offset in tile

    const float* qp = g_q + (size_t)bh * NS * 64;
    const U32* ktp = g_kt + (size_t)bh * 32 * 4096;
    const U32* vtp = g_vt + (size_t)bh * 32 * 4096;
    const U32 sbK = smem_u32(Ks);
    const U32 sbV = smem_u32(Vs);

    auto CPAK = [&](int kb, int st){
        const U32 dK = sbK + st*16384;
        const U32* sK = ktp + (size_t)kb*4096;
        #pragma unroll
        for (int i = 0; i < 8; ++i) {
            int c = i*128 + t;
            cpa16(dK + c*16, sK + c*4);
        }
        asm volatile("cp.async.commit_group;" ::: "memory");
    };
    auto CPAV = [&](int kb){
        const U32* sV = vtp + (size_t)kb*4096;
        #pragma unroll
        for (int i = 0; i < 8; ++i) {
            int c = i*128 + t;
            cpa16(sbV + c*16, sV + c*4);
        }
        asm volatile("cp.async.commit_group;" ::: "memory");
    };

    // ---- stage Q (scaled) into Ps using A-layout ----
    {
        const int r = t >> 1, ksP = t & 1;
        const int mf = r >> 4, g = r & 7, hi = (r >> 3) & 1;
        const int swz = (g >> 1) & 3;
        const float* pq = qp + (size_t)(q0 + r)*64 + ksP*32;
        char* base = Ps + mf*512 + g*64 + hi*4;
        #pragma unroll
        for (int j8 = 0; j8 < 4; ++j8) {
            float4 f0 = *(const float4*)(pq + j8*8);
            float4 f1 = *(const float4*)(pq + j8*8 + 4);
            int ks = ksP*4 + j8;
            float vals[8] = {f0.x,f0.y,f0.z,f0.w,f1.x,f1.y,f1.z,f1.w};
            #pragma unroll
            for (int j = 0; j < 8; ++j) {
                int tg = j & 3, khi = j >> 2;
                *(U32*)(base + ks*2048 + ((tg^swz)<<4) + khi*8) =
                    f2tf(vals[j] * ATT_SCALE);
            }
        }
    }
    CPAK(0, 0);                          // prefetch first K tile
    __syncthreads();

    // ---- Q fragments -> registers ----
    U32 qf[8][4];
    #pragma unroll
    for (int ks = 0; ks < 8; ++ks)
        *(uint4*)qf[ks] =
            *(const uint4*)(Ps + ks*2048 + mfW*512 + grp*64 + (tigA<<4));

    float m_[2], l_[2];
    m_[0] = m_[1] = -1e30f;
    l_[0] = l_[1] = 0.0f;
    float octx[8][4];
    #pragma unroll
    for (int nf=0;nf<8;++nf)
        #pragma unroll
        for (int r=0;r<4;++r) octx[nf][r] = 0.0f;

    for (int kb = 0; kb <= qb; ++kb) {
        const int st = kb & 1;
        CPAV(kb);                        // V for this iter (waited post-softmax)
        if (kb < qb) CPAK(kb + 1, st ^ 1);
        // wait for K(kb): pending = {K(kb), V(kb)[, K(kb+1)]}
        if (kb < qb) asm volatile("cp.async.wait_group 2;" ::: "memory");
        else         asm volatile("cp.async.wait_group 1;" ::: "memory");
        __syncthreads();

        const int k0 = kb * 64;
        const char* Kc = Ks + st*16384 + bco;

        // ---- S = Q @ K^T (paired b-frags, immediate offsets) ----
        float sacc[8][4];
        #pragma unroll
        for (int nf=0;nf<8;++nf)
            #pragma unroll
            for (int r=0;r<4;++r) sacc[nf][r] = 0.0f;
        #pragma unroll
        for (int ks = 0; ks < 8; ++ks) {
            #pragma unroll
            for (int nfp = 0; nfp < 4; ++nfp) {
                uint4 u = *(const uint4*)(Kc + ks*2048 + nfp*512);
                mma8(sacc[2*nfp],     qf[ks], (const U32*)&u.x);
                mma8(sacc[2*nfp + 1], qf[ks], (const U32*)&u.z);
            }
        }

        // ---- online softmax; write P^T in A-layout ----
        const bool diag = (kb == qb);
        #pragma unroll
        for (int l = 0; l < 2; ++l) {
            const int rloc = wr + grp + 8*l;
            const int gi   = q0 + rloc;
            float rm = -1e30f;
            #pragma unroll
            for (int nf = 0; nf < 8; ++nf) {
                #pragma unroll
                for (int c = 0; c < 2; ++c) {
                    float s = sacc[nf][2*l + c];
                    if (diag) {
                        int gj = k0 + nf*8 + 2*tig + c;
                        if (gj >= gi && !(gi == 0 && gj == 0)) s = -1e30f;
                    }
                    sacc[nf][2*l + c] = s;
                    rm = fmaxf(rm, s);
                }
            }
            rm = fmaxf(rm, __shfl_xor_sync(0xffffffffu, rm, 1));
            rm = fmaxf(rm, __shfl_xor_sync(0xffffffffu, rm, 2));
            float mnew = fmaxf(m_[l], rm);
            float fac  = __expf(m_[l] - mnew);
            float ps = 0.0f;
            char* pbase = Ps + mfW*512 + grp*64 + l*4;
            const int swzP = (grp >> 1) & 3;
            #pragma unroll
            for (int nf = 0; nf < 8; ++nf) {
                #pragma unroll
                for (int c = 0; c < 2; ++c) {
                    float p = __expf(sacc[nf][2*l + c] - mnew);
                    int j = 2*tig + c;
                    int tg = j & 3, khi = j >> 2;
                    *(U32*)(pbase + nf*2048 + ((tg^swzP)<<4) + khi*8) = f2tf(p);
                    ps += p;
                }
            }
            ps += __shfl_xor_sync(0xffffffffu, ps, 1);
            ps += __shfl_xor_sync(0xffffffffu, ps, 2);
            l_[l] = l_[l]*fac + ps;
            m_[l] = mnew;
            #pragma unroll
            for (int nf = 0; nf < 8; ++nf) {
                octx[nf][2*l + 0] *= fac;
                octx[nf][2*l + 1] *= fac;
            }
        }

        // ---- wait for V(kb): pending = {V(kb)[, K(kb+1)]} ----
        if (kb < qb) asm volatile("cp.async.wait_group 1;" ::: "memory");
        else         asm volatile("cp.async.wait_group 0;" ::: "memory");
        __syncthreads();                 // V visible to all; also orders Ps

        // ---- ctx += P @ V (paired b-frags) ----
        const char* Vc = Vs + bco;
        #pragma unroll
        for (int ks = 0; ks < 8; ++ks) {
            uint4 af = *(const uint4*)(Ps + ks*2048 + mfW*512
                                          + grp*64 + (tigA<<4));
            #pragma unroll
            for (int nfp = 0; nfp < 4; ++nfp) {
                uint4 u = *(const uint4*)(Vc + ks*2048 + nfp*512);
                mma8(octx[2*nfp],     (const U32*)&af, (const U32*)&u.x);
                mma8(octx[2*nfp + 1], (const U32*)&af, (const U32*)&u.z);
            }
        }
        __syncthreads();                 // Vs safe for next iter's CPAV
    }

    // ---- normalize + write ctx tf32-rounded (head-major) ----
    U32* op = (U32*)(g_ctx + (size_t)bh * NS * 64);
    #pragma unroll
    for (int l = 0; l < 2; ++l) {
        const int r  = q0 + wr + grp + 8*l;
        const float inv = 1.0f / l_[l];
        #pragma unroll
        for (int nf = 0; nf < 8; ++nf) {
            uint2 u;
            u.x = f2tf(octx[nf][2*l + 0] * inv);
            u.y = f2tf(octx[nf][2*l + 1] * inv);
            *(uint2*)(op + (size_t)r*64 + nf*8 + 2*tig) = u;
        }
    }
}

// ---------------------------------------------------------------------------
extern "C" void kernel_launch(void* const* d_in, const int* in_sizes, int n_in,
                              void* d_out, int out_size)
{
    const float* q  = (const float*)d_in[0];
    const float* k  = (const float*)d_in[1];
    const float* v  = (const float*)d_in[2];
    const float* Wq = (const float*)d_in[3];
    const float* Wk = (const float*)d_in[4];
    const float* Wv = (const float*)d_in[5];
    const float* Wo = (const float*)d_in[6];
    float* out = (float*)d_out;

    float *pctx;
    cudaGetSymbolAddress((void**)&pctx, g_ctx);
    U32 *pwo;
    cudaGetSymbolAddress((void**)&pwo, g_woc);

    cudaFuncSetAttribute(flash_mma_kernel,
                         cudaFuncAttributeMaxDynamicSharedMemorySize,
                         FLS_BYTES);

    rope_table_kernel<<<256, 256>>>();
    prep_kernel<<<(3*Q4 + 4*W4)/256, 256>>>((const float4*)q, (const float4*)k,
        (const float4*)v, (const float4*)Wq, (const float4*)Wk,
        (const float4*)Wv, (const float4*)Wo);

    dim3 gq(NE/128, NM/128, 3);            // (8, 32, 3): Q,K,V in one launch
    qkv_mma<<<gq, 256>>>();

    dim3 fg(NS/64, NB*NH);                 // (32, 32)
    flash_mma_kernel<<<fg, 128, FLS_BYTES>>>();

    dim3 gg(NE/128, NM/128);               // (8, 32)
    gemm_mma<<<gg, 256>>>((const U32*)pctx, pwo, out, 1, 0, 0);  // output proj
}

// round 16
// speedup vs baseline: 1.2357x; 1.0233x over previous
#include <cuda_runtime.h>
#include <math.h>

typedef unsigned long long ULL;
typedef unsigned int U32;

#define NB 2
#define NS 2048
#define NE 1024
#define NH 16
#define NHD 64
#define NM 4096                  // NB*NS
#define ATT_SCALE (1.0f/32.0f)   // 1/sqrt(1024), exact power of two

// ---------------- scratch (device globals; no allocation allowed) ----------
__device__ float g_ctx[NB*NH*NS*NHD];  // written tf32-rounded by flash
__device__ float g_cos[NS*32];
__device__ float g_sin[NS*32];
// pre-converted tf32-bit operands
__device__ U32 g_qc[NM*NE];
__device__ U32 g_kc[NM*NE];
__device__ U32 g_vc[NM*NE];
__device__ U32 g_wqc[NE*NE];
__device__ U32 g_wkc[NE*NE];
__device__ U32 g_wvc[NE*NE];
__device__ U32 g_woc[NE*NE];
// Q packed into flash A-layout images (pre-scaled): [bh][qb][4096 U32]
__device__ U32 g_qt[NB*NH*32*4096];
// K/V packed into flash paired-b-frag images: [bh][kb][4096 U32]
__device__ U32 g_kt[NB*NH*32*4096];
__device__ U32 g_vt[NB*NH*32*4096];

// ---------------- helpers ---------------------------------------------------
__device__ __forceinline__ U32 f2tf(float x){
    U32 u; asm("cvt.rn.tf32.f32 %0, %1;" : "=r"(u) : "f"(x)); return u;
}
__device__ __forceinline__ void mma8(float* c, const U32* a, const U32* b){
    asm volatile("mma.sync.aligned.m16n8k8.row.col.f32.tf32.tf32.f32 "
        "{%0,%1,%2,%3}, {%4,%5,%6,%7}, {%8,%9}, {%0,%1,%2,%3};"
        : "+f"(c[0]), "+f"(c[1]), "+f"(c[2]), "+f"(c[3])
        : "r"(a[0]), "r"(a[1]), "r"(a[2]), "r"(a[3]), "r"(b[0]), "r"(b[1]));
}
__device__ __forceinline__ U32 smem_u32(const void* p){
    U32 a;
    asm("{ .reg .u64 t; cvta.to.shared.u64 t, %1; cvt.u32.u64 %0, t; }"
        : "=r"(a) : "l"(p));
    return a;
}
__device__ __forceinline__ void ldsm4(U32* r, U32 a){
    asm volatile("ldmatrix.sync.aligned.m8n8.x4.shared.b16 {%0,%1,%2,%3}, [%4];"
        : "=r"(r[0]), "=r"(r[1]), "=r"(r[2]), "=r"(r[3]) : "r"(a));
}
__device__ __forceinline__ void ldsm2(U32* r, U32 a){
    asm volatile("ldmatrix.sync.aligned.m8n8.x2.shared.b16 {%0,%1}, [%2];"
        : "=r"(r[0]), "=r"(r[1]) : "r"(a));
}
__device__ __forceinline__ void cpa16(U32 dst, const void* src){
    asm volatile("cp.async.cg.shared.global [%0], [%1], 16;"
                 :: "r"(dst), "l"(src) : "memory");
}

// ---------------- prep: fp32 -> tf32 bits (RN) + rope table ------------------
#define Q4 (NM*NE/4)
#define W4 (NE*NE/4)
__global__ void prep_kernel(const float4* __restrict__ q, const float4* __restrict__ k,
                            const float4* __restrict__ v, const float4* __restrict__ wq,
                            const float4* __restrict__ wk, const float4* __restrict__ wv,
                            const float4* __restrict__ wo)
{
    int i = blockIdx.x * blockDim.x + threadIdx.x;
    if (i < NS*32) {                       // fused rope table
        int s = i >> 5, p = i & 31;
        double invf = 1.0 / pow(10000.0, (double)(2*p) / 64.0);
        double a = (double)s * invf;
        g_cos[i] = (float)cos(a);
        g_sin[i] = (float)sin(a);
    }
    const float4* s; uint4* d;
    if      (i <   Q4) { s = q + i;        d = (uint4*)g_qc + i; }
    else if (i < 2*Q4) { s = k + (i-Q4);   d = (uint4*)g_kc + (i-Q4); }
    else if (i < 3*Q4) { s = v + (i-2*Q4); d = (uint4*)g_vc + (i-2*Q4); }
    else {
        int j = i - 3*Q4, w = j / W4, o = j - w*W4;
        const float4* ws[4] = {wq, wk, wv, wo};
        uint4* wd[4] = {(uint4*)g_wqc, (uint4*)g_wkc, (uint4*)g_wvc, (uint4*)g_woc};
        s = ws[w] + o; d = wd[w] + o;
    }
    float4 f = *s;
    *d = make_uint4(f2tf(f.x), f2tf(f.y), f2tf(f.z), f2tf(f.w));
}

// ============================================================================
// Projection GEMM body: cp.async 4-stage (distance-3) + ldmatrix, BK=16.
// 256 thr = 8 warps (2x4), warp tile 64x32. Static smem 64KB.
// Epilogue modes: 0=plain C [m][n]; 2=K packed g_kt; 3=V packed g_vt;
//                 4=Q packed g_qt (pre-scaled, A-layout).
// ============================================================================
#define PST 16384

__device__ __forceinline__ void gemm_body(
    const U32* __restrict__ A, const U32* __restrict__ Wt,
    float* __restrict__ C, int a_heads, int mode, int do_rope)
{
    __shared__ __align__(128) char smem[4*PST];
    const U32 sb0 = smem_u32(smem);
    const int t    = threadIdx.x;
    const int lane = t & 31;
    const int wid  = t >> 5;
    const int grp  = lane >> 2;
    const int tig  = lane & 3;
    const int wm   = (wid & 1) * 64;
    const int wn   = (wid >> 1) * 32;
    const int bm   = blockIdx.y * 128;
    const int bn   = blockIdx.x * 128;

    const int prA = t >> 1, prH = t & 1;
    const U32 dsw0 = prA*64 + (((2*prH    ) ^ ((prA>>1)&3)) << 4);
    const U32 dsw1 = prA*64 + (((2*prH + 1) ^ ((prA>>1)&3)) << 4);

    const int rlA = (lane & 7) | (((lane >> 3) & 1) << 3);
    const int cbA = (lane >> 4) & 1;
    const U32 offA = sb0 + (wm + rlA)*64 + ((cbA ^ ((rlA>>1)&3)) << 4);
    const int rlB = lane & 7;
    const int cbB = (lane >> 3) & 1;
    const U32 offB = sb0 + 8192 + (wn + rlB)*64 + ((cbB ^ ((rlB>>1)&3)) << 4);

    float acc[4][4][4];
    #pragma unroll
    for (int i=0;i<4;++i)
        #pragma unroll
        for (int j=0;j<4;++j)
            #pragma unroll
            for (int r=0;r<4;++r) acc[i][j][r] = 0.0f;

    auto CPA = [&](int kt, int st){
        const U32 sA = sb0 + st*PST;
        const U32 sB = sA + 8192;
        const int e0 = kt*16 + prH*8;
        const U32* pa;
        if (!a_heads) pa = A + (size_t)(bm + prA)*NE + e0;
        else {
            int m = bm + prA, b = m >> 11, s = m & 2047;
            pa = A + ((size_t)((b*16 + (e0 >> 6))*NS + s))*64 + (e0 & 63);
        }
        const U32* pb = Wt + (size_t)(bn + prA)*NE + e0;
        cpa16(sA + dsw0, pa);     cpa16(sA + dsw1, pa + 4);
        cpa16(sB + dsw0, pb);     cpa16(sB + dsw1, pb + 4);
        asm volatile("cp.async.commit_group;" ::: "memory");
    };

    auto MMA = [&](int st){
        const U32 bA = offA + st*PST;
        const U32 bB = offB + st*PST;
        #pragma unroll
        for (int ks = 0; ks < 2; ++ks) {
            U32 af[4][4];
            #pragma unroll
            for (int mf = 0; mf < 4; ++mf)
                ldsm4(af[mf], (bA + mf*1024) ^ (ks << 5));
            U32 bf[4][2];
            #pragma unroll
            for (int nf = 0; nf < 4; ++nf)
                ldsm2(bf[nf], (bB + nf*512) ^ (ks << 5));
            #pragma unroll
            for (int mf = 0; mf < 4; ++mf)
                #pragma unroll
                for (int nf = 0; nf < 4; ++nf)
                    mma8(acc[mf][nf], af[mf], bf[nf]);
        }
    };

    CPA(0, 0); CPA(1, 1); CPA(2, 2);
    for (int kt = 0; kt < 64; ++kt) {
        if      (kt < 62) asm volatile("cp.async.wait_group 2;" ::: "memory");
        else if (kt < 63) asm volatile("cp.async.wait_group 1;" ::: "memory");
        else              asm volatile("cp.async.wait_group 0;" ::: "memory");
        __syncthreads();
        if (kt < 61) CPA(kt + 3, (kt + 3) & 3);
        MMA(kt & 3);
    }

    // epilogue (+ optional fused RoPE: (fx,fy) = one (even,odd) hd pair)
    #pragma unroll
    for (int mf = 0; mf < 4; ++mf) {
        #pragma unroll
        for (int half = 0; half < 2; ++half) {
            int m = bm + wm + mf*16 + grp + half*8;
            #pragma unroll
            for (int nf = 0; nf < 4; ++nf) {
                int n = bn + wn + nf*8 + 2*tig;
                float fx = acc[mf][nf][half*2 + 0];
                float fy = acc[mf][nf][half*2 + 1];
                if (do_rope) {
                    int s = m & 2047;
                    int p = (n & 63) >> 1;
                    float co = g_cos[s*32 + p], sn = g_sin[s*32 + p];
                    float rx = fx*co - fy*sn;
                    float ry = fx*sn + fy*co;
                    fx = rx; fy = ry;
                }
                if (mode == 0) {
                    *(float2*)(C + (size_t)m*NE + n) = make_float2(fx, fy);
                } else if (mode == 2) {
                    // K packed: element K[s][hd] -> paired-b-frag layout
                    int b = m >> 11, s2 = m & 2047;
                    int h = n >> 6, hd = n & 63;
                    U32* base = g_kt + ((size_t)((b*16 + h)*32 + (s2>>6)))*4096;
                    int c = s2 & 63;
                    int wb = (c>>4)*128 + (c&7)*16 + ((c>>3)&1)*2;
                    {
                        int ks = hd >> 3, j = hd & 7;
                        base[ks*512 + wb + (j&3)*4 + (j>>2)] = f2tf(fx);
                    }
                    {
                        int hd1 = hd + 1;
                        int ks = hd1 >> 3, j = hd1 & 7;
                        base[ks*512 + wb + (j&3)*4 + (j>>2)] = f2tf(fy);
                    }
                } else if (mode == 3) {
                    // V packed: element V[s][hd] -> paired-b-frag layout
                    int b = m >> 11, s2 = m & 2047;
                    int h = n >> 6, hd = n & 63;
                    U32* base = g_vt + ((size_t)((b*16 + h)*32 + (s2>>6)))*4096;
                    int c = s2 & 63, j = c & 7;
                    int kofs = (c>>3)*512 + (j&3)*4 + (j>>2);
                    base[kofs + (hd>>4)*128 + (hd&7)*16 + ((hd>>3)&1)*2] = f2tf(fx);
                    int hd1 = hd + 1;
                    base[kofs + (hd1>>4)*128 + (hd1&7)*16 + ((hd1>>3)&1)*2] = f2tf(fy);
                } else {
                    // Q packed: element Q[s][hd] -> A-layout, pre-scaled
                    int b = m >> 11, s2 = m & 2047;
                    int h = n >> 6, hd = n & 63;
                    U32* base = g_qt + ((size_t)((b*16 + h)*32 + (s2>>6)))*4096;
                    int r = s2 & 63;
                    int mfq = r >> 4, g = r & 7, hi = (r >> 3) & 1;
                    int swz = (g >> 1) & 3;
                    int rofs = mfq*128 + g*16 + hi;
                    {
                        int ks = hd >> 3, j = hd & 7, tg = j & 3, khi = j >> 2;
                        base[ks*512 + rofs + (((tg^swz)<<2)) + khi*2]
                            = f2tf(fx * ATT_SCALE);
                    }
                    {
                        int hd1 = hd + 1;
                        int ks = hd1 >> 3, j = hd1 & 7, tg = j & 3, khi = j >> 2;
                        base[ks*512 + rofs + (((tg^swz)<<2)) + khi*2]
                            = f2tf(fy * ATT_SCALE);
                    }
                }
            }
        }
    }
}

// combined QKV launch: blockIdx.z selects projection
__global__ void __launch_bounds__(256, 2)
qkv_mma()
{
    const int z = blockIdx.z;
    const U32* A = (z == 0) ? g_qc : (z == 1) ? g_kc : g_vc;
    const U32* W = (z == 0) ? g_wqc : (z == 1) ? g_wkc : g_wvc;
    const int mode = (z == 0) ? 4 : (z == 1) ? 2 : 3;
    gemm_body(A, W, nullptr, 0, mode, (z < 2) ? 1 : 0);
}

__global__ void __launch_bounds__(256, 2)
gemm_mma(const U32* __restrict__ A, const U32* __restrict__ Wt,
         float* __restrict__ C, int a_heads, int mode, int do_rope)
{
    gemm_body(A, Wt, C, a_heads, mode, do_rope);
}

// ============================================================================
// Flash attention v7: Q tile cp.async'd from pre-packed g_qt (pre-scaled
// A-layout). Paired-b-frag K/V. Ks double-buffered, Vs single buffer, Ps.
// 64KB smem -> 3 CTAs/SM. Tile 64x64, 128 thr = 4 warps.
// ============================================================================
#define FLS_BYTES (4*16384)      // Ks[2] 32KB + Vs 16KB + Ps 16KB

__global__ void __launch_bounds__(128, 3)
flash_mma_kernel()
{
    extern __shared__ __align__(128) char fsm[];
    char* Ks = fsm;                      // 2 stages x 16KB
    char* Vs = fsm + 32768;              // 1 stage  x 16KB
    char* Ps = fsm + 49152;              // A-layout P^T; doubles as Q landing

    const int t    = threadIdx.x;
    const int lane = t & 31;
    const int wid  = t >> 5;
    const int grp  = lane >> 2;
    const int tig  = lane & 3;
    const int wr   = wid * 16;
    const int mfW  = wid;
    const int tigA = tig ^ ((grp >> 1) & 3);
    const int bh   = blockIdx.y;
    const int qb   = (int)gridDim.x - 1 - (int)blockIdx.x;  // heavy first
    const int q0   = qb * 64;
    const U32 bco  = (U32)(grp*64 + tig*16);   // b-frag byte offset in tile

    const U32* qtp = g_qt + ((size_t)bh*32 + qb)*4096;
    const U32* ktp = g_kt + (size_t)bh * 32 * 4096;
    const U32* vtp = g_vt + (size_t)bh * 32 * 4096;
    const U32 sbK = smem_u32(Ks);
    const U32 sbV = smem_u32(Vs);
    const U32 sbP = smem_u32(Ps);

    auto CPAK = [&](int kb, int st){
        const U32 dK = sbK + st*16384;
        const U32* sK = ktp + (size_t)kb*4096;
        #pragma unroll
        for (int i = 0; i < 8; ++i) {
            int c = i*128 + t;
            cpa16(dK + c*16, sK + c*4);
        }
        asm volatile("cp.async.commit_group;" ::: "memory");
    };
    auto CPAV = [&](int kb){
        const U32* sV = vtp + (size_t)kb*4096;
        #pragma unroll
        for (int i = 0; i < 8; ++i) {
            int c = i*128 + t;
            cpa16(sbV + c*16, sV + c*4);
        }
        asm volatile("cp.async.commit_group;" ::: "memory");
    };

    // ---- Q tile -> Ps via cp.async (group #1), K0 (group #2) ----
    {
        #pragma unroll
        for (int i = 0; i < 8; ++i) {
            int c = i*128 + t;
            cpa16(sbP + c*16, qtp + c*4);
        }
        asm volatile("cp.async.commit_group;" ::: "memory");
    }
    CPAK(0, 0);
    asm volatile("cp.async.wait_group 1;" ::: "memory");   // Q done, K0 pending
    __syncthreads();

    // ---- Q fragments -> registers ----
    U32 qf[8][4];
    #pragma unroll
    for (int ks = 0; ks < 8; ++ks)
        *(uint4*)qf[ks] =
            *(const uint4*)(Ps + ks*2048 + mfW*512 + grp*64 + (tigA<<4));

    float m_[2], l_[2];
    m_[0] = m_[1] = -1e30f;
    l_[0] = l_[1] = 0.0f;
    float octx[8][4];
    #pragma unroll
    for (int nf=0;nf<8;++nf)
        #pragma unroll
        for (int r=0;r<4;++r) octx[nf][r] = 0.0f;

    for (int kb = 0; kb <= qb; ++kb) {
        const int st = kb & 1;
        CPAV(kb);                        // V for this iter (waited post-softmax)
        if (kb < qb) CPAK(kb + 1, st ^ 1);
        // wait for K(kb): pending = {K(kb), V(kb)[, K(kb+1)]}
        if (kb < qb) asm volatile("cp.async.wait_group 2;" ::: "memory");
        else         asm volatile("cp.async.wait_group 1;" ::: "memory");
        __syncthreads();

        const int k0 = kb * 64;
        const char* Kc = Ks + st*16384 + bco;

        // ---- S = Q @ K^T (paired b-frags, immediate offsets) ----
        float sacc[8][4];
        #pragma unroll
        for (int nf=0;nf<8;++nf)
            #pragma unroll
            for (int r=0;r<4;++r) sacc[nf][r] = 0.0f;
        #pragma unroll
        for (int ks = 0; ks < 8; ++ks) {
            #pragma unroll
            for (int nfp = 0; nfp < 4; ++nfp) {
                uint4 u = *(const uint4*)(Kc + ks*2048 + nfp*512);
                mma8(sacc[2*nfp],     qf[ks], (const U32*)&u.x);
                mma8(sacc[2*nfp + 1], qf[ks], (const U32*)&u.z);
            }
        }

        // ---- online softmax; write P^T in A-layout ----
        const bool diag = (kb == qb);
        #pragma unroll
        for (int l = 0; l < 2; ++l) {
            const int rloc = wr + grp + 8*l;
            const int gi   = q0 + rloc;
            float rm = -1e30f;
            #pragma unroll
            for (int nf = 0; nf < 8; ++nf) {
                #pragma unroll
                for (int c = 0; c < 2; ++c) {
                    float s = sacc[nf][2*l + c];
                    if (diag) {
                        int gj = k0 + nf*8 + 2*tig + c;
                        if (gj >= gi && !(gi == 0 && gj == 0)) s = -1e30f;
                    }
                    sacc[nf][2*l + c] = s;
                    rm = fmaxf(rm, s);
                }
            }
            rm = fmaxf(rm, __shfl_xor_sync(0xffffffffu, rm, 1));
            rm = fmaxf(rm, __shfl_xor_sync(0xffffffffu, rm, 2));
            float mnew = fmaxf(m_[l], rm);
            float fac  = __expf(m_[l] - mnew);
            float ps = 0.0f;
            char* pbase = Ps + mfW*512 + grp*64 + l*4;
            const int swzP = (grp >> 1) & 3;
            #pragma unroll
            for (int nf = 0; nf < 8; ++nf) {
                #pragma unroll
                for (int c = 0; c < 2; ++c) {
                    float p = __expf(sacc[nf][2*l + c] - mnew);
                    int j = 2*tig + c;
                    int tg = j & 3, khi = j >> 2;
                    *(U32*)(pbase + nf*2048 + ((tg^swzP)<<4) + khi*8) = f2tf(p);
                    ps += p;
                }
            }
            ps += __shfl_xor_sync(0xffffffffu, ps, 1);
            ps += __shfl_xor_sync(0xffffffffu, ps, 2);
            l_[l] = l_[l]*fac + ps;
            m_[l] = mnew;
            #pragma unroll
            for (int nf = 0; nf < 8; ++nf) {
                octx[nf][2*l + 0] *= fac;
                octx[nf][2*l + 1] *= fac;
            }
        }

        // ---- wait for V(kb): pending = {V(kb)[, K(kb+1)]} ----
        if (kb < qb) asm volatile("cp.async.wait_group 1;" ::: "memory");
        else         asm volatile("cp.async.wait_group 0;" ::: "memory");
        __syncthreads();                 // V visible to all; also orders Ps

        // ---- ctx += P @ V (paired b-frags) ----
        const char* Vc = Vs + bco;
        #pragma unroll
        for (int ks = 0; ks < 8; ++ks) {
            uint4 af = *(const uint4*)(Ps + ks*2048 + mfW*512
                                          + grp*64 + (tigA<<4));
            #pragma unroll
            for (int nfp = 0; nfp < 4; ++nfp) {
                uint4 u = *(const uint4*)(Vc + ks*2048 + nfp*512);
                mma8(octx[2*nfp],     (const U32*)&af, (const U32*)&u.x);
                mma8(octx[2*nfp + 1], (const U32*)&af, (const U32*)&u.z);
            }
        }
        __syncthreads();                 // Vs safe for next iter's CPAV
    }

    // ---- normalize + write ctx tf32-rounded (head-major) ----
    U32* op = (U32*)(g_ctx + (size_t)bh * NS * 64);
    #pragma unroll
    for (int l = 0; l < 2; ++l) {
        const int r  = q0 + wr + grp + 8*l;
        const float inv = 1.0f / l_[l];
        #pragma unroll
        for (int nf = 0; nf < 8; ++nf) {
            uint2 u;
            u.x = f2tf(octx[nf][2*l + 0] * inv);
            u.y = f2tf(octx[nf][2*l + 1] * inv);
            *(uint2*)(op + (size_t)r*64 + nf*8 + 2*tig) = u;
        }
    }
}

// ---------------------------------------------------------------------------
extern "C" void kernel_launch(void* const* d_in, const int* in_sizes, int n_in,
                              void* d_out, int out_size)
{
    const float* q  = (const float*)d_in[0];
    const float* k  = (const float*)d_in[1];
    const float* v  = (const float*)d_in[2];
    const float* Wq = (const float*)d_in[3];
    const float* Wk = (const float*)d_in[4];
    const float* Wv = (const float*)d_in[5];
    const float* Wo = (const float*)d_in[6];
    float* out = (float*)d_out;

    float *pctx;
    cudaGetSymbolAddress((void**)&pctx, g_ctx);
    U32 *pwo;
    cudaGetSymbolAddress((void**)&pwo, g_woc);

    cudaFuncSetAttribute(flash_mma_kernel,
                         cudaFuncAttributeMaxDynamicSharedMemorySize,
                         FLS_BYTES);

    prep_kernel<<<(3*Q4 + 4*W4)/256, 256>>>((const float4*)q, (const float4*)k,
        (const float4*)v, (const float4*)Wq, (const float4*)Wk,
        (const float4*)Wv, (const float4*)Wo);

    dim3 gq(NE/128, NM/128, 3);            // (8, 32, 3): Q,K,V in one launch
    qkv_mma<<<gq, 256>>>();

    dim3 fg(NS/64, NB*NH);                 // (32, 32)
    flash_mma_kernel<<<fg, 128, FLS_BYTES>>>();

    dim3 gg(NE/128, NM/128);               // (8, 32)
    gemm_mma<<<gg, 256>>>((const U32*)pctx, pwo, out, 1, 0, 0);  // output proj
}

// round 17
// speedup vs baseline: 1.2523x; 1.0134x over previous
#include <cuda_runtime.h>
#include <math.h>

typedef unsigned long long ULL;
typedef unsigned int U32;

#define NB 2
#define NS 2048
#define NE 1024
#define NH 16
#define NHD 64
#define NM 4096                  // NB*NS
#define ATT_SCALE (1.0f/32.0f)   // 1/sqrt(1024), exact power of two

// ---------------- scratch (device globals; no allocation allowed) ----------
__device__ float g_ctx[NB*NH*NS*NHD];  // written tf32-rounded by flash
__device__ float g_cos[NS*32];
__device__ float g_sin[NS*32];
// pre-converted tf32-bit operands
__device__ U32 g_qc[NM*NE];
__device__ U32 g_kc[NM*NE];
__device__ U32 g_vc[NM*NE];
__device__ U32 g_wqc[NE*NE];
__device__ U32 g_wkc[NE*NE];
__device__ U32 g_wvc[NE*NE];
__device__ U32 g_woc[NE*NE];
// Q packed into flash A-layout images (pre-scaled): [bh][qb][4096 U32]
__device__ U32 g_qt[NB*NH*32*4096];
// K/V packed into flash paired-b-frag images: [bh][kb][4096 U32]
__device__ U32 g_kt[NB*NH*32*4096];
__device__ U32 g_vt[NB*NH*32*4096];

// ---------------- helpers ---------------------------------------------------
__device__ __forceinline__ U32 f2tf(float x){
    U32 u; asm("cvt.rn.tf32.f32 %0, %1;" : "=r"(u) : "f"(x)); return u;
}
__device__ __forceinline__ void mma8(float* c, const U32* a, const U32* b){
    asm volatile("mma.sync.aligned.m16n8k8.row.col.f32.tf32.tf32.f32 "
        "{%0,%1,%2,%3}, {%4,%5,%6,%7}, {%8,%9}, {%0,%1,%2,%3};"
        : "+f"(c[0]), "+f"(c[1]), "+f"(c[2]), "+f"(c[3])
        : "r"(a[0]), "r"(a[1]), "r"(a[2]), "r"(a[3]), "r"(b[0]), "r"(b[1]));
}
__device__ __forceinline__ U32 smem_u32(const void* p){
    U32 a;
    asm("{ .reg .u64 t; cvta.to.shared.u64 t, %1; cvt.u32.u64 %0, t; }"
        : "=r"(a) : "l"(p));
    return a;
}
__device__ __forceinline__ void ldsm4(U32* r, U32 a){
    asm volatile("ldmatrix.sync.aligned.m8n8.x4.shared.b16 {%0,%1,%2,%3}, [%4];"
        : "=r"(r[0]), "=r"(r[1]), "=r"(r[2]), "=r"(r[3]) : "r"(a));
}
__device__ __forceinline__ void ldsm2(U32* r, U32 a){
    asm volatile("ldmatrix.sync.aligned.m8n8.x2.shared.b16 {%0,%1}, [%2];"
        : "=r"(r[0]), "=r"(r[1]) : "r"(a));
}
__device__ __forceinline__ void cpa16(U32 dst, const void* src){
    asm volatile("cp.async.cg.shared.global [%0], [%1], 16;"
                 :: "r"(dst), "l"(src) : "memory");
}

// ---------------- prep: fp32 -> tf32 bits (RN) + rope table ------------------
#define Q4 (NM*NE/4)
#define W4 (NE*NE/4)
__global__ void prep_kernel(const float4* __restrict__ q, const float4* __restrict__ k,
                            const float4* __restrict__ v, const float4* __restrict__ wq,
                            const float4* __restrict__ wk, const float4* __restrict__ wv,
                            const float4* __restrict__ wo)
{
    int i = blockIdx.x * blockDim.x + threadIdx.x;
    if (i < NS*32) {                       // fused rope table
        int s = i >> 5, p = i & 31;
        double invf = 1.0 / pow(10000.0, (double)(2*p) / 64.0);
        double a = (double)s * invf;
        g_cos[i] = (float)cos(a);
        g_sin[i] = (float)sin(a);
    }
    const float4* s; uint4* d;
    if      (i <   Q4) { s = q + i;        d = (uint4*)g_qc + i; }
    else if (i < 2*Q4) { s = k + (i-Q4);   d = (uint4*)g_kc + (i-Q4); }
    else if (i < 3*Q4) { s = v + (i-2*Q4); d = (uint4*)g_vc + (i-2*Q4); }
    else {
        int j = i - 3*Q4, w = j / W4, o = j - w*W4;
        const float4* ws[4] = {wq, wk, wv, wo};
        uint4* wd[4] = {(uint4*)g_wqc, (uint4*)g_wkc, (uint4*)g_wvc, (uint4*)g_woc};
        s = ws[w] + o; d = wd[w] + o;
    }
    float4 f = *s;
    *d = make_uint4(f2tf(f.x), f2tf(f.y), f2tf(f.z), f2tf(f.w));
}

// ============================================================================
// Projection GEMM body: cp.async 4-stage (distance-3) + ldmatrix, BK=16.
// 256 thr = 8 warps (2x4), warp tile 64x32. Static smem 64KB.
// Epilogue modes: 0=plain C [m][n]; 2=K packed g_kt; 3=V packed g_vt;
//                 4=Q packed g_qt (pre-scaled, A-layout).
// ============================================================================
#define PST 16384

__device__ __forceinline__ void gemm_body(
    const U32* __restrict__ A, const U32* __restrict__ Wt,
    float* __restrict__ C, int a_heads, int mode, int do_rope)
{
    __shared__ __align__(128) char smem[4*PST];
    const U32 sb0 = smem_u32(smem);
    const int t    = threadIdx.x;
    const int lane = t & 31;
    const int wid  = t >> 5;
    const int grp  = lane >> 2;
    const int tig  = lane & 3;
    const int wm   = (wid & 1) * 64;
    const int wn   = (wid >> 1) * 32;
    const int bm   = blockIdx.y * 128;
    const int bn   = blockIdx.x * 128;

    const int prA = t >> 1, prH = t & 1;
    const U32 dsw0 = prA*64 + (((2*prH    ) ^ ((prA>>1)&3)) << 4);
    const U32 dsw1 = prA*64 + (((2*prH + 1) ^ ((prA>>1)&3)) << 4);

    const int rlA = (lane & 7) | (((lane >> 3) & 1) << 3);
    const int cbA = (lane >> 4) & 1;
    const U32 offA = sb0 + (wm + rlA)*64 + ((cbA ^ ((rlA>>1)&3)) << 4);
    const int rlB = lane & 7;
    const int cbB = (lane >> 3) & 1;
    const U32 offB = sb0 + 8192 + (wn + rlB)*64 + ((cbB ^ ((rlB>>1)&3)) << 4);

    float acc[4][4][4];
    #pragma unroll
    for (int i=0;i<4;++i)
        #pragma unroll
        for (int j=0;j<4;++j)
            #pragma unroll
            for (int r=0;r<4;++r) acc[i][j][r] = 0.0f;

    auto CPA = [&](int kt, int st){
        const U32 sA = sb0 + st*PST;
        const U32 sB = sA + 8192;
        const int e0 = kt*16 + prH*8;
        const U32* pa;
        if (!a_heads) pa = A + (size_t)(bm + prA)*NE + e0;
        else {
            int m = bm + prA, b = m >> 11, s = m & 2047;
            pa = A + ((size_t)((b*16 + (e0 >> 6))*NS + s))*64 + (e0 & 63);
        }
        const U32* pb = Wt + (size_t)(bn + prA)*NE + e0;
        cpa16(sA + dsw0, pa);     cpa16(sA + dsw1, pa + 4);
        cpa16(sB + dsw0, pb);     cpa16(sB + dsw1, pb + 4);
        asm volatile("cp.async.commit_group;" ::: "memory");
    };

    auto MMA = [&](int st){
        const U32 bA = offA + st*PST;
        const U32 bB = offB + st*PST;
        #pragma unroll
        for (int ks = 0; ks < 2; ++ks) {
            U32 af[4][4];
            #pragma unroll
            for (int mf = 0; mf < 4; ++mf)
                ldsm4(af[mf], (bA + mf*1024) ^ (ks << 5));
            U32 bf[4][2];
            #pragma unroll
            for (int nf = 0; nf < 4; ++nf)
                ldsm2(bf[nf], (bB + nf*512) ^ (ks << 5));
            #pragma unroll
            for (int mf = 0; mf < 4; ++mf)
                #pragma unroll
                for (int nf = 0; nf < 4; ++nf)
                    mma8(acc[mf][nf], af[mf], bf[nf]);
        }
    };

    CPA(0, 0); CPA(1, 1); CPA(2, 2);
    for (int kt = 0; kt < 64; ++kt) {
        if      (kt < 62) asm volatile("cp.async.wait_group 2;" ::: "memory");
        else if (kt < 63) asm volatile("cp.async.wait_group 1;" ::: "memory");
        else              asm volatile("cp.async.wait_group 0;" ::: "memory");
        __syncthreads();
        if (kt < 61) CPA(kt + 3, (kt + 3) & 3);
        MMA(kt & 3);
    }

    // epilogue (+ optional fused RoPE: (fx,fy) = one (even,odd) hd pair)
    #pragma unroll
    for (int mf = 0; mf < 4; ++mf) {
        #pragma unroll
        for (int half = 0; half < 2; ++half) {
            int m = bm + wm + mf*16 + grp + half*8;
            #pragma unroll
            for (int nf = 0; nf < 4; ++nf) {
                int n = bn + wn + nf*8 + 2*tig;
                float fx = acc[mf][nf][half*2 + 0];
                float fy = acc[mf][nf][half*2 + 1];
                if (do_rope) {
                    int s = m & 2047;
                    int p = (n & 63) >> 1;
                    float co = g_cos[s*32 + p], sn = g_sin[s*32 + p];
                    float rx = fx*co - fy*sn;
                    float ry = fx*sn + fy*co;
                    fx = rx; fy = ry;
                }
                if (mode == 0) {
                    *(float2*)(C + (size_t)m*NE + n) = make_float2(fx, fy);
                } else if (mode == 2) {
                    // K packed: element K[s][hd] -> paired-b-frag layout
                    int b = m >> 11, s2 = m & 2047;
                    int h = n >> 6, hd = n & 63;
                    U32* base = g_kt + ((size_t)((b*16 + h)*32 + (s2>>6)))*4096;
                    int c = s2 & 63;
                    int wb = (c>>4)*128 + (c&7)*16 + ((c>>3)&1)*2;
                    {
                        int ks = hd >> 3, j = hd & 7;
                        base[ks*512 + wb + (j&3)*4 + (j>>2)] = f2tf(fx);
                    }
                    {
                        int hd1 = hd + 1;
                        int ks = hd1 >> 3, j = hd1 & 7;
                        base[ks*512 + wb + (j&3)*4 + (j>>2)] = f2tf(fy);
                    }
                } else if (mode == 3) {
                    // V packed: element V[s][hd] -> paired-b-frag layout
                    int b = m >> 11, s2 = m & 2047;
                    int h = n >> 6, hd = n & 63;
                    U32* base = g_vt + ((size_t)((b*16 + h)*32 + (s2>>6)))*4096;
                    int c = s2 & 63, j = c & 7;
                    int kofs = (c>>3)*512 + (j&3)*4 + (j>>2);
                    base[kofs + (hd>>4)*128 + (hd&7)*16 + ((hd>>3)&1)*2] = f2tf(fx);
                    int hd1 = hd + 1;
                    base[kofs + (hd1>>4)*128 + (hd1&7)*16 + ((hd1>>3)&1)*2] = f2tf(fy);
                } else {
                    // Q packed: element Q[s][hd] -> A-layout, pre-scaled
                    int b = m >> 11, s2 = m & 2047;
                    int h = n >> 6, hd = n & 63;
                    U32* base = g_qt + ((size_t)((b*16 + h)*32 + (s2>>6)))*4096;
                    int r = s2 & 63;
                    int mfq = r >> 4, g = r & 7, hi = (r >> 3) & 1;
                    int swz = (g >> 1) & 3;
                    int rofs = mfq*128 + g*16 + hi;
                    {
                        int ks = hd >> 3, j = hd & 7, tg = j & 3, khi = j >> 2;
                        base[ks*512 + rofs + (((tg^swz)<<2)) + khi*2]
                            = f2tf(fx * ATT_SCALE);
                    }
                    {
                        int hd1 = hd + 1;
                        int ks = hd1 >> 3, j = hd1 & 7, tg = j & 3, khi = j >> 2;
                        base[ks*512 + rofs + (((tg^swz)<<2)) + khi*2]
                            = f2tf(fy * ATT_SCALE);
                    }
                }
            }
        }
    }
}

// combined QKV launch: blockIdx.z selects projection
__global__ void __launch_bounds__(256, 2)
qkv_mma()
{
    const int z = blockIdx.z;
    const U32* A = (z == 0) ? g_qc : (z == 1) ? g_kc : g_vc;
    const U32* W = (z == 0) ? g_wqc : (z == 1) ? g_wkc : g_wvc;
    const int mode = (z == 0) ? 4 : (z == 1) ? 2 : 3;
    gemm_body(A, W, nullptr, 0, mode, (z < 2) ? 1 : 0);
}

__global__ void __launch_bounds__(256, 2)
gemm_mma(const U32* __restrict__ A, const U32* __restrict__ Wt,
         float* __restrict__ C, int a_heads, int mode, int do_rope)
{
    gemm_body(A, Wt, C, a_heads, mode, do_rope);
}

// ============================================================================
// Flash attention v8: as v7 plus fused P^T stores — both row-halves (l=0/1)
// of a (nf,c) are adjacent words in the Ps A-layout, so 16x STS.32 becomes
// 8x STS.64 emitted after the softmax math (p values parked in dead sacc).
// ============================================================================
#define FLS_BYTES (4*16384)      // Ks[2] 32KB + Vs 16KB + Ps 16KB

__global__ void __launch_bounds__(128, 3)
flash_mma_kernel()
{
    extern __shared__ __align__(128) char fsm[];
    char* Ks = fsm;                      // 2 stages x 16KB
    char* Vs = fsm + 32768;              // 1 stage  x 16KB
    char* Ps = fsm + 49152;              // A-layout P^T; doubles as Q landing

    const int t    = threadIdx.x;
    const int lane = t & 31;
    const int wid  = t >> 5;
    const int grp  = lane >> 2;
    const int tig  = lane & 3;
    const int wr   = wid * 16;
    const int mfW  = wid;
    const int tigA = tig ^ ((grp >> 1) & 3);
    const int bh   = blockIdx.y;
    const int qb   = (int)gridDim.x - 1 - (int)blockIdx.x;  // heavy first
    const int q0   = qb * 64;
    const U32 bco  = (U32)(grp*64 + tig*16);   // b-frag byte offset in tile

    const U32* qtp = g_qt + ((size_t)bh*32 + qb)*4096;
    const U32* ktp = g_kt + (size_t)bh * 32 * 4096;
    const U32* vtp = g_vt + (size_t)bh * 32 * 4096;
    const U32 sbK = smem_u32(Ks);
    const U32 sbV = smem_u32(Vs);
    const U32 sbP = smem_u32(Ps);

    auto CPAK = [&](int kb, int st){
        const U32 dK = sbK + st*16384;
        const U32* sK = ktp + (size_t)kb*4096;
        #pragma unroll
        for (int i = 0; i < 8; ++i) {
            int c = i*128 + t;
            cpa16(dK + c*16, sK + c*4);
        }
        asm volatile("cp.async.commit_group;" ::: "memory");
    };
    auto CPAV = [&](int kb){
        const U32* sV = vtp + (size_t)kb*4096;
        #pragma unroll
        for (int i = 0; i < 8; ++i) {
            int c = i*128 + t;
            cpa16(sbV + c*16, sV + c*4);
        }
        asm volatile("cp.async.commit_group;" ::: "memory");
    };

    // ---- Q tile -> Ps via cp.async (group #1), K0 (group #2) ----
    {
        #pragma unroll
        for (int i = 0; i < 8; ++i) {
            int c = i*128 + t;
            cpa16(sbP + c*16, qtp + c*4);
        }
        asm volatile("cp.async.commit_group;" ::: "memory");
    }
    CPAK(0, 0);
    asm volatile("cp.async.wait_group 1;" ::: "memory");   // Q done, K0 pending
    __syncthreads();

    // ---- Q fragments -> registers ----
    U32 qf[8][4];
    #pragma unroll
    for (int ks = 0; ks < 8; ++ks)
        *(uint4*)qf[ks] =
            *(const uint4*)(Ps + ks*2048 + mfW*512 + grp*64 + (tigA<<4));

    float m_[2], l_[2];
    m_[0] = m_[1] = -1e30f;
    l_[0] = l_[1] = 0.0f;
    float octx[8][4];
    #pragma unroll
    for (int nf=0;nf<8;++nf)
        #pragma unroll
        for (int r=0;r<4;++r) octx[nf][r] = 0.0f;

    for (int kb = 0; kb <= qb; ++kb) {
        const int st = kb & 1;
        CPAV(kb);                        // V for this iter (waited post-softmax)
        if (kb < qb) CPAK(kb + 1, st ^ 1);
        // wait for K(kb): pending = {K(kb), V(kb)[, K(kb+1)]}
        if (kb < qb) asm volatile("cp.async.wait_group 2;" ::: "memory");
        else         asm volatile("cp.async.wait_group 1;" ::: "memory");
        __syncthreads();

        const int k0 = kb * 64;
        const char* Kc = Ks + st*16384 + bco;

        // ---- S = Q @ K^T (paired b-frags, immediate offsets) ----
        float sacc[8][4];
        #pragma unroll
        for (int nf=0;nf<8;++nf)
            #pragma unroll
            for (int r=0;r<4;++r) sacc[nf][r] = 0.0f;
        #pragma unroll
        for (int ks = 0; ks < 8; ++ks) {
            #pragma unroll
            for (int nfp = 0; nfp < 4; ++nfp) {
                uint4 u = *(const uint4*)(Kc + ks*2048 + nfp*512);
                mma8(sacc[2*nfp],     qf[ks], (const U32*)&u.x);
                mma8(sacc[2*nfp + 1], qf[ks], (const U32*)&u.z);
            }
        }

        // ---- online softmax (p values parked back into sacc) ----
        const bool diag = (kb == qb);
        #pragma unroll
        for (int l = 0; l < 2; ++l) {
            const int rloc = wr + grp + 8*l;
            const int gi   = q0 + rloc;
            float rm = -1e30f;
            #pragma unroll
            for (int nf = 0; nf < 8; ++nf) {
                #pragma unroll
                for (int c = 0; c < 2; ++c) {
                    float s = sacc[nf][2*l + c];
                    if (diag) {
                        int gj = k0 + nf*8 + 2*tig + c;
                        if (gj >= gi && !(gi == 0 && gj == 0)) s = -1e30f;
                    }
                    sacc[nf][2*l + c] = s;
                    rm = fmaxf(rm, s);
                }
            }
            rm = fmaxf(rm, __shfl_xor_sync(0xffffffffu, rm, 1));
            rm = fmaxf(rm, __shfl_xor_sync(0xffffffffu, rm, 2));
            float mnew = fmaxf(m_[l], rm);
            float fac  = __expf(m_[l] - mnew);
            float ps = 0.0f;
            #pragma unroll
            for (int nf = 0; nf < 8; ++nf) {
                #pragma unroll
                for (int c = 0; c < 2; ++c) {
                    float p = __expf(sacc[nf][2*l + c] - mnew);
                    sacc[nf][2*l + c] = p;       // park for fused store
                    ps += p;
                }
            }
            ps += __shfl_xor_sync(0xffffffffu, ps, 1);
            ps += __shfl_xor_sync(0xffffffffu, ps, 2);
            l_[l] = l_[l]*fac + ps;
            m_[l] = mnew;
            #pragma unroll
            for (int nf = 0; nf < 8; ++nf) {
                octx[nf][2*l + 0] *= fac;
                octx[nf][2*l + 1] *= fac;
            }
        }

        // ---- fused P^T stores: 8x STS.64 (l=0,1 adjacent words) ----
        {
            char* pbase = Ps + mfW*512 + grp*64;
            const int swzP = (grp >> 1) & 3;
            #pragma unroll
            for (int c = 0; c < 2; ++c) {
                int j = 2*tig + c;
                int tg = j & 3, khi = j >> 2;
                char* paddr = pbase + ((tg^swzP)<<4) + khi*8;
                #pragma unroll
                for (int nf = 0; nf < 8; ++nf) {
                    uint2 u;
                    u.x = f2tf(sacc[nf][c]);         // l=0
                    u.y = f2tf(sacc[nf][2 + c]);     // l=1
                    *(uint2*)(paddr + nf*2048) = u;
                }
            }
        }

        // ---- wait for V(kb): pending = {V(kb)[, K(kb+1)]} ----
        if (kb < qb) asm volatile("cp.async.wait_group 1;" ::: "memory");
        else         asm volatile("cp.async.wait_group 0;" ::: "memory");
        __syncthreads();                 // V visible to all; also orders Ps

        // ---- ctx += P @ V (paired b-frags) ----
        const char* Vc = Vs + bco;
        #pragma unroll
        for (int ks = 0; ks < 8; ++ks) {
            uint4 af = *(const uint4*)(Ps + ks*2048 + mfW*512
                                          + grp*64 + (tigA<<4));
            #pragma unroll
            for (int nfp = 0; nfp < 4; ++nfp) {
                uint4 u = *(const uint4*)(Vc + ks*2048 + nfp*512);
                mma8(octx[2*nfp],     (const U32*)&af, (const U32*)&u.x);
                mma8(octx[2*nfp + 1], (const U32*)&af, (const U32*)&u.z);
            }
        }
        __syncthreads();                 // Vs safe for next iter's CPAV
    }

    // ---- normalize + write ctx tf32-rounded (head-major) ----
    U32* op = (U32*)(g_ctx + (size_t)bh * NS * 64);
    #pragma unroll
    for (int l = 0; l < 2; ++l) {
        const int r  = q0 + wr + grp + 8*l;
        const float inv = 1.0f / l_[l];
        #pragma unroll
        for (int nf = 0; nf < 8; ++nf) {
            uint2 u;
            u.x = f2tf(octx[nf][2*l + 0] * inv);
            u.y = f2tf(octx[nf][2*l + 1] * inv);
            *(uint2*)(op + (size_t)r*64 + nf*8 + 2*tig) = u;
        }
    }
}

// ---------------------------------------------------------------------------
extern "C" void kernel_launch(void* const* d_in, const int* in_sizes, int n_in,
                              void* d_out, int out_size)
{
    const float* q  = (const float*)d_in[0];
    const float* k  = (const float*)d_in[1];
    const float* v  = (const float*)d_in[2];
    const float* Wq = (const float*)d_in[3];
    const float* Wk = (const float*)d_in[4];
    const float* Wv = (const float*)d_in[5];
    const float* Wo = (const float*)d_in[6];
    float* out = (float*)d_out;

    float *pctx;
    cudaGetSymbolAddress((void**)&pctx, g_ctx);
    U32 *pwo;
    cudaGetSymbolAddress((void**)&pwo, g_woc);

    cudaFuncSetAttribute(flash_mma_kernel,
                         cudaFuncAttributeMaxDynamicSharedMemorySize,
                         FLS_BYTES);

    prep_kernel<<<(3*Q4 + 4*W4)/256, 256>>>((const float4*)q, (const float4*)k,
        (const float4*)v, (const float4*)Wq, (const float4*)Wk,
        (const float4*)Wv, (const float4*)Wo);

    dim3 gq(NE/128, NM/128, 3);            // (8, 32, 3): Q,K,V in one launch
    qkv_mma<<<gq, 256>>>();

    dim3 fg(NS/64, NB*NH);                 // (32, 32)
    flash_mma_kernel<<<fg, 128, FLS_BYTES>>>();

    dim3 gg(NE/128, NM/128);               // (8, 32)
    gemm_mma<<<gg, 256>>>((const U32*)pctx, pwo, out, 1, 0, 0);  // output proj
}